// round 2
// baseline (speedup 1.0000x reference)
#include <cuda_runtime.h>
#include <cuda_bf16.h>
#include <cstdint>

#define NB_ 8
#define C_ 64
#define HID_ 128
#define HW_ 65536

// Scratch (device globals; no allocation in kernel_launch)
__device__ __nv_bfloat16 g_h1[(size_t)NB_ * HID_ * HW_];
__device__ __nv_bfloat16 g_h2[(size_t)NB_ * HID_ * HW_];
__device__ float g_pool_part[NB_ * HID_ * 64];
__device__ float g_attn[NB_ * HID_];

#define MMA_BF16(d, A, b0r, b1r)                                              \
  asm volatile(                                                               \
      "mma.sync.aligned.m16n8k16.row.col.f32.bf16.bf16.f32 "                  \
      "{%0,%1,%2,%3},{%4,%5,%6,%7},{%8,%9},{%0,%1,%2,%3};\n"                  \
      : "+f"((d)[0]), "+f"((d)[1]), "+f"((d)[2]), "+f"((d)[3])                \
      : "r"((A)[0]), "r"((A)[1]), "r"((A)[2]), "r"((A)[3]), "r"(b0r),         \
        "r"(b1r))

__device__ __forceinline__ unsigned ldu(const __nv_bfloat16* p) {
  return *reinterpret_cast<const unsigned*>(p);
}

// ---------------------------------------------------------------------------
// K1: LayerNorm + 1x1 conv (64->256, bf16 mma) + SimpleGate -> g_h1 (bf16)
// Block: 128 pixels, 512 threads (16 warps as 4M x 4N-pairhalves)
// ---------------------------------------------------------------------------
#define K1_OFF_W 0          // w1 bf16 [256][66]          = 33792 B
#define K1_OFF_A 33792      // xn bf16 [128][66]          = 16896 B
#define K1_OFF_B1 50688     // b1 f32  [256]              =  1024 B
#define K1_OFF_RED 51712    // LN partials f32 [1024]     =  4096 B
#define K1_OFF_H 55808      // h1 stage bf16 [128][130]   = 33280 B
#define K1_SMEM 89088

__global__ void __launch_bounds__(512, 1)
k1_ln_gemm_gate(const float* __restrict__ x, const float* __restrict__ ln_w,
                const float* __restrict__ ln_b, const float* __restrict__ w1,
                const float* __restrict__ b1) {
  extern __shared__ char sm1[];
  __nv_bfloat16* sW = (__nv_bfloat16*)(sm1 + K1_OFF_W);
  __nv_bfloat16* sA = (__nv_bfloat16*)(sm1 + K1_OFF_A);
  float* sB1 = (float*)(sm1 + K1_OFF_B1);
  float* sRED = (float*)(sm1 + K1_OFF_RED);
  __nv_bfloat16* sH = (__nv_bfloat16*)(sm1 + K1_OFF_H);

  const int tid = threadIdx.x;
  const int b = blockIdx.x >> 9;               // 512 blocks per image
  const int pix0 = (blockIdx.x & 511) << 7;    // 128 pixels per block

  // weights -> smem (bf16)
  for (int i = tid; i < 256 * 64; i += 512)
    sW[(i >> 6) * 66 + (i & 63)] = __float2bfloat16(w1[i]);
  if (tid < 256) sB1[tid] = b1[tid];

  // load x tile + LayerNorm (4 threads per pixel, 16 channels each)
  const int p = tid & 127, q = tid >> 7;
  const float* xb = x + (size_t)b * C_ * HW_ + (size_t)(q * 16) * HW_ + pix0 + p;
  float v[16], s1 = 0.f, s2 = 0.f;
#pragma unroll
  for (int i = 0; i < 16; i++) {
    float t = xb[(size_t)i * HW_];
    v[i] = t;
    s1 += t;
    s2 += t * t;
  }
  sRED[tid] = s1;
  sRED[512 + tid] = s2;
  __syncthreads();
  float t1 = sRED[p] + sRED[128 + p] + sRED[256 + p] + sRED[384 + p];
  float t2 = sRED[512 + p] + sRED[640 + p] + sRED[768 + p] + sRED[896 + p];
  float mean = t1 * (1.f / 64.f);
  float var = t2 * (1.f / 64.f) - mean * mean;
  float rstd = rsqrtf(var + 1e-6f);
#pragma unroll
  for (int i = 0; i < 16; i++) {
    int c = q * 16 + i;
    float xn = (v[i] - mean) * rstd * ln_w[c] + ln_b[c];
    sA[p * 66 + c] = __float2bfloat16(xn);
  }
  __syncthreads();

  // mma: block tile M=128, N=256 (pairs). warp tile M=32, Npair=32+32
  const int lane = tid & 31, wid = tid >> 5;
  const int lr = lane >> 2, lc = lane & 3;
  const int MB = (wid & 3) * 32;
  const int NBc = (wid >> 2) * 32;

  float acc1[2][4][4], acc2[2][4][4];
#pragma unroll
  for (int mt = 0; mt < 2; mt++)
#pragma unroll
    for (int nt = 0; nt < 4; nt++)
#pragma unroll
      for (int r = 0; r < 4; r++) {
        acc1[mt][nt][r] = 0.f;
        acc2[mt][nt][r] = 0.f;
      }

#pragma unroll
  for (int ks = 0; ks < 4; ks++) {
    const int ca = ks * 16 + lc * 2;
    unsigned a[2][4];
#pragma unroll
    for (int mt = 0; mt < 2; mt++) {
      int r0 = MB + mt * 16 + lr;
      a[mt][0] = ldu(&sA[r0 * 66 + ca]);
      a[mt][1] = ldu(&sA[(r0 + 8) * 66 + ca]);
      a[mt][2] = ldu(&sA[r0 * 66 + ca + 8]);
      a[mt][3] = ldu(&sA[(r0 + 8) * 66 + ca + 8]);
    }
#pragma unroll
    for (int nt = 0; nt < 4; nt++) {
      int n1 = NBc + nt * 8 + lr;
      unsigned b0 = ldu(&sW[n1 * 66 + ca]);
      unsigned b1r = ldu(&sW[n1 * 66 + ca + 8]);
      MMA_BF16(acc1[0][nt], a[0], b0, b1r);
      MMA_BF16(acc1[1][nt], a[1], b0, b1r);
      int n2 = n1 + 128;
      unsigned c0 = ldu(&sW[n2 * 66 + ca]);
      unsigned c1r = ldu(&sW[n2 * 66 + ca + 8]);
      MMA_BF16(acc2[0][nt], a[0], c0, c1r);
      MMA_BF16(acc2[1][nt], a[1], c0, c1r);
    }
  }

  // gate in-register, stage [ch][pixel] in smem
#pragma unroll
  for (int mt = 0; mt < 2; mt++)
#pragma unroll
    for (int nt = 0; nt < 4; nt++)
#pragma unroll
      for (int r = 0; r < 4; r++) {
        int row = MB + mt * 16 + lr + ((r & 2) ? 8 : 0);
        int col = NBc + nt * 8 + lc * 2 + (r & 1);
        float y1 = acc1[mt][nt][r] + sB1[col];
        float y2 = acc2[mt][nt][r] + sB1[col + 128];
        sH[col * 130 + row] = __float2bfloat16(y1 * y2);
      }
  __syncthreads();

  // coalesced write-out (u32 = 2 pixels)
  const unsigned* sHu = (const unsigned*)sH;
  unsigned* outu = (unsigned*)g_h1;
  size_t baseu = (((size_t)b * HID_) * HW_ + pix0) >> 1;
  for (int i = tid; i < 128 * 64; i += 512) {
    int ch = i >> 6, j = i & 63;
    outu[baseu + (size_t)ch * (HW_ / 2) + j] = sHu[ch * 65 + j];
  }
}

// ---------------------------------------------------------------------------
// K2: grouped 3x3 depthwise (2 out per group) + gate + pool partials
// h2[j] = (conv(h1[j/2], w2[j]) + b2[j]) * (conv(h1[64+j/2], w2[128+j]) + b2[128+j])
// block: channel-pair c -> outputs j=2c,2c+1; 32x32 spatial tile with halo
// ---------------------------------------------------------------------------
__global__ void __launch_bounds__(256)
k2_dwconv_gate_pool(const float* __restrict__ w2, const float* __restrict__ b2) {
  __shared__ __nv_bfloat16 sI0[34 * 36];
  __shared__ __nv_bfloat16 sI1[34 * 36];
  __shared__ float sws[36];
  __shared__ float sbs[4];
  __shared__ float sred[512];

  const int tile = blockIdx.x;  // 0..63 (8x8 of 32x32)
  const int c = blockIdx.y;     // 0..63
  const int b = blockIdx.z;     // 0..7
  const int ty0 = (tile >> 3) * 32 - 1;
  const int tx0 = (tile & 7) * 32 - 1;
  const int tid = threadIdx.x;

  if (tid < 36) {
    int widx = tid / 9, t = tid % 9;
    int o = (widx < 2) ? (2 * c + widx) : (128 + 2 * c + (widx - 2));
    sws[tid] = w2[o * 9 + t];
  } else if (tid < 40) {
    int widx = tid - 36;
    int o = (widx < 2) ? (2 * c + widx) : (128 + 2 * c + (widx - 2));
    sbs[widx] = b2[o];
  }

  const __nv_bfloat16* i0 = g_h1 + ((size_t)(b * HID_ + c)) * HW_;
  const __nv_bfloat16* i1 = g_h1 + ((size_t)(b * HID_ + 64 + c)) * HW_;
  for (int i = tid; i < 34 * 34; i += 256) {
    int y = i / 34, xx = i - y * 34;
    int gy = ty0 + y, gx = tx0 + xx;
    bool ok = ((unsigned)gy < 256u) && ((unsigned)gx < 256u);
    sI0[y * 36 + xx] = ok ? i0[gy * 256 + gx] : __float2bfloat16(0.f);
    sI1[y * 36 + xx] = ok ? i1[gy * 256 + gx] : __float2bfloat16(0.f);
  }
  __syncthreads();

  float sum0 = 0.f, sum1 = 0.f;
  const int rr = tid >> 4;
  const int px0 = (tid & 15) * 2;
#pragma unroll
  for (int pass = 0; pass < 2; pass++) {
    int row = rr + pass * 16;
    float a00 = 0, a01 = 0, a10 = 0, a11 = 0, c00 = 0, c01 = 0, c10 = 0, c11 = 0;
#pragma unroll
    for (int dy = 0; dy < 3; dy++) {
#pragma unroll
      for (int dx = 0; dx < 3; dx++) {
        float w0 = sws[dy * 3 + dx], w1v = sws[9 + dy * 3 + dx];
        float w2v = sws[18 + dy * 3 + dx], w3v = sws[27 + dy * 3 + dx];
        float i0a = __bfloat162float(sI0[(row + dy) * 36 + px0 + dx]);
        float i0b = __bfloat162float(sI0[(row + dy) * 36 + px0 + 1 + dx]);
        float i1a = __bfloat162float(sI1[(row + dy) * 36 + px0 + dx]);
        float i1b = __bfloat162float(sI1[(row + dy) * 36 + px0 + 1 + dx]);
        a00 += w0 * i0a;  a01 += w0 * i0b;
        a10 += w1v * i0a; a11 += w1v * i0b;
        c00 += w2v * i1a; c01 += w2v * i1b;
        c10 += w3v * i1a; c11 += w3v * i1b;
      }
    }
    float h0a = (a00 + sbs[0]) * (c00 + sbs[2]);
    float h0b = (a01 + sbs[0]) * (c01 + sbs[2]);
    float h1a = (a10 + sbs[1]) * (c10 + sbs[3]);
    float h1b = (a11 + sbs[1]) * (c11 + sbs[3]);
    sum0 += h0a + h0b;
    sum1 += h1a + h1b;
    int gy = ty0 + 1 + row, gx = tx0 + 1 + px0;
    size_t base0 = ((size_t)(b * HID_ + 2 * c)) * HW_ + gy * 256 + gx;
    __nv_bfloat162 pk0, pk1;
    pk0.x = __float2bfloat16(h0a); pk0.y = __float2bfloat16(h0b);
    pk1.x = __float2bfloat16(h1a); pk1.y = __float2bfloat16(h1b);
    *(__nv_bfloat162*)(&g_h2[base0]) = pk0;
    *(__nv_bfloat162*)(&g_h2[base0 + HW_]) = pk1;
  }

  // deterministic per-tile pool partials (no atomics)
  sred[tid] = sum0;
  sred[256 + tid] = sum1;
  __syncthreads();
  for (int s = 128; s > 0; s >>= 1) {
    if (tid < s) {
      sred[tid] += sred[tid + s];
      sred[256 + tid] += sred[256 + tid + s];
    }
    __syncthreads();
  }
  if (tid == 0) {
    g_pool_part[(b * HID_ + 2 * c) * 64 + tile] = sred[0];
    g_pool_part[(b * HID_ + 2 * c + 1) * 64 + tile] = sred[256];
  }
}

// ---------------------------------------------------------------------------
// K3: attention matvec: attn[b][o] = b_sca[o] + sum_c w_sca[o][c]*mean_pool[b][c]
// ---------------------------------------------------------------------------
__global__ void k3_attn(const float* __restrict__ w_sca,
                        const float* __restrict__ b_sca) {
  __shared__ float sp[HID_];
  int b = blockIdx.x;
  int o = threadIdx.x;
  float s = 0.f;
  const float* pp = g_pool_part + (b * HID_ + o) * 64;
#pragma unroll 8
  for (int t = 0; t < 64; t++) s += pp[t];
  sp[o] = s * (1.f / 65536.f);
  __syncthreads();
  float acc = b_sca[o];
  const float* w = w_sca + o * HID_;
#pragma unroll 8
  for (int cc = 0; cc < HID_; cc++) acc += w[cc] * sp[cc];
  g_attn[b * HID_ + o] = acc;
}

// ---------------------------------------------------------------------------
// K4: (h2*attn) @ w3^T + b3, out = x + beta*h3. attn folded into weights.
// Block: 128 pixels x 64 out-channels, K=128. 256 threads (8 warps: 2M x 4N)
// ---------------------------------------------------------------------------
#define K4_OFF_A 0       // h2 bf16 [128 px][132]   = 33792 B
#define K4_OFF_W 33792   // w3*attn bf16 [64][132]  = 16896 B
#define K4_OFF_AT 50688  // attn f32 [128]          =   512 B
#define K4_OFF_O 51200   // out stage f32 [64][132] = 33792 B
#define K4_SMEM 84992

__global__ void __launch_bounds__(256)
k4_gemm_residual(const float* __restrict__ w3, const float* __restrict__ b3,
                 const float* __restrict__ beta, const float* __restrict__ x,
                 float* __restrict__ out) {
  extern __shared__ char sm4[];
  __nv_bfloat16* sA = (__nv_bfloat16*)(sm4 + K4_OFF_A);
  __nv_bfloat16* sWB = (__nv_bfloat16*)(sm4 + K4_OFF_W);
  float* sAt = (float*)(sm4 + K4_OFF_AT);
  float* sO = (float*)(sm4 + K4_OFF_O);

  const int tid = threadIdx.x;
  const int b = blockIdx.x >> 9;
  const int pix0 = (blockIdx.x & 511) << 7;

  if (tid < 128) sAt[tid] = g_attn[b * HID_ + tid];

  // load h2 tile with transpose -> sA[pixel][ch]
  const unsigned* h2u = (const unsigned*)g_h2;
  size_t baseu = (((size_t)b * HID_) * HW_ + pix0) >> 1;
  for (int i = tid; i < 128 * 64; i += 256) {
    int ch = i >> 6, j = i & 63;
    unsigned uv = h2u[baseu + (size_t)ch * (HW_ / 2) + j];
    __nv_bfloat162 v2 = *(__nv_bfloat162*)&uv;
    sA[(2 * j) * 132 + ch] = v2.x;
    sA[(2 * j + 1) * 132 + ch] = v2.y;
  }
  __syncthreads();  // sAt ready, sA ready
  for (int i = tid; i < 64 * 128; i += 256) {
    int o = i >> 7, k = i & 127;
    sWB[o * 132 + k] = __float2bfloat16(w3[i] * sAt[k]);
  }
  __syncthreads();

  const int lane = tid & 31, wid = tid >> 5;
  const int lr = lane >> 2, lc = lane & 3;
  const int MB = (wid & 1) * 32;    // out-channel tile
  const int NBp = (wid >> 1) * 32;  // pixel tile

  float acc[2][4][4];
#pragma unroll
  for (int mt = 0; mt < 2; mt++)
#pragma unroll
    for (int nt = 0; nt < 4; nt++)
#pragma unroll
      for (int r = 0; r < 4; r++) acc[mt][nt][r] = 0.f;

#pragma unroll
  for (int ks = 0; ks < 8; ks++) {
    int ca = ks * 16 + lc * 2;
    unsigned a[2][4];
#pragma unroll
    for (int mt = 0; mt < 2; mt++) {
      int r0 = MB + mt * 16 + lr;
      a[mt][0] = ldu(&sWB[r0 * 132 + ca]);
      a[mt][1] = ldu(&sWB[(r0 + 8) * 132 + ca]);
      a[mt][2] = ldu(&sWB[r0 * 132 + ca + 8]);
      a[mt][3] = ldu(&sWB[(r0 + 8) * 132 + ca + 8]);
    }
#pragma unroll
    for (int nt = 0; nt < 4; nt++) {
      int n = NBp + nt * 8 + lr;
      unsigned b0 = ldu(&sA[n * 132 + ca]);
      unsigned b1r = ldu(&sA[n * 132 + ca + 8]);
      MMA_BF16(acc[0][nt], a[0], b0, b1r);
      MMA_BF16(acc[1][nt], a[1], b0, b1r);
    }
  }

#pragma unroll
  for (int mt = 0; mt < 2; mt++)
#pragma unroll
    for (int nt = 0; nt < 4; nt++)
#pragma unroll
      for (int r = 0; r < 4; r++) {
        int row = MB + mt * 16 + lr + ((r & 2) ? 8 : 0);
        int col = NBp + nt * 8 + lc * 2 + (r & 1);
        sO[row * 132 + col] = acc[mt][nt][r];
      }
  __syncthreads();

  size_t xbase = ((size_t)b * C_) * HW_ + pix0;
  for (int i = tid; i < 64 * 128; i += 256) {
    int o = i >> 7, pc = i & 127;
    float hval = sO[o * 132 + pc] + b3[o];
    size_t idx = xbase + (size_t)o * HW_ + pc;
    out[idx] = x[idx] + hval * beta[o];
  }
}

// ---------------------------------------------------------------------------
extern "C" void kernel_launch(void* const* d_in, const int* in_sizes, int n_in,
                              void* d_out, int out_size) {
  const float* x = (const float*)d_in[0];
  const float* ln_w = (const float*)d_in[1];
  const float* ln_b = (const float*)d_in[2];
  const float* w1 = (const float*)d_in[3];
  const float* b1 = (const float*)d_in[4];
  const float* w2 = (const float*)d_in[5];
  const float* b2 = (const float*)d_in[6];
  const float* w_sca = (const float*)d_in[7];
  const float* b_sca = (const float*)d_in[8];
  const float* w3 = (const float*)d_in[9];
  const float* b3 = (const float*)d_in[10];
  const float* beta = (const float*)d_in[11];
  float* out = (float*)d_out;

  cudaFuncSetAttribute(k1_ln_gemm_gate,
                       cudaFuncAttributeMaxDynamicSharedMemorySize, K1_SMEM);
  cudaFuncSetAttribute(k4_gemm_residual,
                       cudaFuncAttributeMaxDynamicSharedMemorySize, K4_SMEM);

  k1_ln_gemm_gate<<<4096, 512, K1_SMEM>>>(x, ln_w, ln_b, w1, b1);
  k2_dwconv_gate_pool<<<dim3(64, 64, 8), 256>>>(w2, b2);
  k3_attn<<<8, 128>>>(w_sca, b_sca);
  k4_gemm_residual<<<4096, 256, K4_SMEM>>>(w3, b3, beta, x, out);
}

// round 4
// speedup vs baseline: 1.3265x; 1.3265x over previous
#include <cuda_runtime.h>
#include <cuda_bf16.h>
#include <cstdint>

#define NB_ 8
#define C_ 64
#define HID_ 128
#define HW_ 65536

// Scratch (device globals; no allocation in kernel_launch)
__device__ __nv_bfloat16 g_h1[(size_t)NB_ * HID_ * HW_];
__device__ __nv_bfloat16 g_h2[(size_t)NB_ * HID_ * HW_];
__device__ float g_pool_part[NB_ * HID_ * 16];
__device__ float g_attn[NB_ * HID_];

#define MMA_BF16(d, A, b0r, b1r)                                              \
  asm volatile(                                                               \
      "mma.sync.aligned.m16n8k16.row.col.f32.bf16.bf16.f32 "                  \
      "{%0,%1,%2,%3},{%4,%5,%6,%7},{%8,%9},{%0,%1,%2,%3};\n"                  \
      : "+f"((d)[0]), "+f"((d)[1]), "+f"((d)[2]), "+f"((d)[3])                \
      : "r"((A)[0]), "r"((A)[1]), "r"((A)[2]), "r"((A)[3]), "r"(b0r),         \
        "r"(b1r))

__device__ __forceinline__ unsigned ldu(const __nv_bfloat16* p) {
  return *reinterpret_cast<const unsigned*>(p);
}

// ---------------------------------------------------------------------------
// K1: LayerNorm + 1x1 conv (64->256, bf16 mma) + SimpleGate -> g_h1 (bf16)
// Block: 128 pixels, 512 threads (16 warps as 4M x 4N-pairhalves)
// Strides padded for bank-conflict-free mma operand loads (72 = 36 words/row)
// ---------------------------------------------------------------------------
#define K1_OFF_W 0          // w1 bf16 [256][72]          = 36864 B
#define K1_OFF_A 36864      // xn bf16 [128][72]          = 18432 B
#define K1_OFF_B1 55296     // b1 f32  [256]              =  1024 B
#define K1_OFF_RED 56320    // LN partials f32 [1024]     =  4096 B
#define K1_OFF_H 60416      // h1 stage bf16 [128][132]   = 33792 B
#define K1_SMEM 94208

__global__ void __launch_bounds__(512, 1)
k1_ln_gemm_gate(const float* __restrict__ x, const float* __restrict__ ln_w,
                const float* __restrict__ ln_b, const float* __restrict__ w1,
                const float* __restrict__ b1) {
  extern __shared__ char sm1[];
  __nv_bfloat16* sW = (__nv_bfloat16*)(sm1 + K1_OFF_W);
  __nv_bfloat16* sA = (__nv_bfloat16*)(sm1 + K1_OFF_A);
  float* sB1 = (float*)(sm1 + K1_OFF_B1);
  float* sRED = (float*)(sm1 + K1_OFF_RED);
  __nv_bfloat16* sH = (__nv_bfloat16*)(sm1 + K1_OFF_H);

  const int tid = threadIdx.x;
  const int b = blockIdx.x >> 9;               // 512 blocks per image
  const int pix0 = (blockIdx.x & 511) << 7;    // 128 pixels per block

  // weights -> smem (bf16)
  for (int i = tid; i < 256 * 64; i += 512)
    sW[(i >> 6) * 72 + (i & 63)] = __float2bfloat16(w1[i]);
  if (tid < 256) sB1[tid] = b1[tid];

  // load x tile + LayerNorm (4 threads per pixel, 16 channels each)
  const int p = tid & 127, q = tid >> 7;
  const float* xb = x + (size_t)b * C_ * HW_ + (size_t)(q * 16) * HW_ + pix0 + p;
  float v[16], s1 = 0.f, s2 = 0.f;
#pragma unroll
  for (int i = 0; i < 16; i++) {
    float t = xb[(size_t)i * HW_];
    v[i] = t;
    s1 += t;
    s2 += t * t;
  }
  sRED[tid] = s1;
  sRED[512 + tid] = s2;
  __syncthreads();
  float t1 = sRED[p] + sRED[128 + p] + sRED[256 + p] + sRED[384 + p];
  float t2 = sRED[512 + p] + sRED[640 + p] + sRED[768 + p] + sRED[896 + p];
  float mean = t1 * (1.f / 64.f);
  float var = t2 * (1.f / 64.f) - mean * mean;
  float rstd = rsqrtf(var + 1e-6f);
#pragma unroll
  for (int i = 0; i < 16; i++) {
    int c = q * 16 + i;
    float xn = (v[i] - mean) * rstd * ln_w[c] + ln_b[c];
    sA[p * 72 + c] = __float2bfloat16(xn);
  }
  __syncthreads();

  // mma: block tile M=128px, Npair=128 (both gate halves). warp M=32, Npair=32
  const int lane = tid & 31, wid = tid >> 5;
  const int lr = lane >> 2, lc = lane & 3;
  const int MB = (wid & 3) * 32;
  const int NBc = (wid >> 2) * 32;

  float acc1[2][4][4], acc2[2][4][4];
#pragma unroll
  for (int mt = 0; mt < 2; mt++)
#pragma unroll
    for (int nt = 0; nt < 4; nt++)
#pragma unroll
      for (int r = 0; r < 4; r++) {
        acc1[mt][nt][r] = 0.f;
        acc2[mt][nt][r] = 0.f;
      }

#pragma unroll
  for (int ks = 0; ks < 4; ks++) {
    const int ca = ks * 16 + lc * 2;
    unsigned a[2][4];
#pragma unroll
    for (int mt = 0; mt < 2; mt++) {
      int r0 = MB + mt * 16 + lr;
      a[mt][0] = ldu(&sA[r0 * 72 + ca]);
      a[mt][1] = ldu(&sA[(r0 + 8) * 72 + ca]);
      a[mt][2] = ldu(&sA[r0 * 72 + ca + 8]);
      a[mt][3] = ldu(&sA[(r0 + 8) * 72 + ca + 8]);
    }
#pragma unroll
    for (int nt = 0; nt < 4; nt++) {
      int n1 = NBc + nt * 8 + lr;
      unsigned b0 = ldu(&sW[n1 * 72 + ca]);
      unsigned b1r = ldu(&sW[n1 * 72 + ca + 8]);
      MMA_BF16(acc1[0][nt], a[0], b0, b1r);
      MMA_BF16(acc1[1][nt], a[1], b0, b1r);
      int n2 = n1 + 128;
      unsigned c0 = ldu(&sW[n2 * 72 + ca]);
      unsigned c1r = ldu(&sW[n2 * 72 + ca + 8]);
      MMA_BF16(acc2[0][nt], a[0], c0, c1r);
      MMA_BF16(acc2[1][nt], a[1], c0, c1r);
    }
  }

  // gate in-register, stage [ch][pixel] in smem
#pragma unroll
  for (int mt = 0; mt < 2; mt++)
#pragma unroll
    for (int nt = 0; nt < 4; nt++)
#pragma unroll
      for (int r = 0; r < 4; r++) {
        int row = MB + mt * 16 + lr + ((r & 2) ? 8 : 0);
        int col = NBc + nt * 8 + lc * 2 + (r & 1);
        float y1 = acc1[mt][nt][r] + sB1[col];
        float y2 = acc2[mt][nt][r] + sB1[col + 128];
        sH[col * 132 + row] = __float2bfloat16(y1 * y2);
      }
  __syncthreads();

  // coalesced write-out (uint2 = 4 pixels)
  const uint2* sH2 = (const uint2*)sH;            // stride 33 uint2/row
  uint2* out2 = (uint2*)g_h1;
  size_t base2 = (((size_t)b * HID_) * HW_ + pix0) >> 2;
  for (int i = tid; i < 128 * 32; i += 512) {
    int ch = i >> 5, j2 = i & 31;
    out2[base2 + (size_t)ch * (HW_ / 4) + j2] = sH2[ch * 33 + j2];
  }
}

// ---------------------------------------------------------------------------
// K2: grouped 3x3 depthwise (2 out per group) + gate + pool partials
// Full-width row tiles: 256 wide x 16 high; halo only in y (x-halo = border 0).
// 256 threads: thread = 4x4 output micro-tile, register row sliding.
// ---------------------------------------------------------------------------
__global__ void __launch_bounds__(256)
k2_dwconv_gate_pool(const float* __restrict__ w2, const float* __restrict__ b2) {
  __shared__ __nv_bfloat16 sI[2][18 * 272];  // data at cols 8..263, row 16B-aligned
  __shared__ float swb[40];
  __shared__ float sred[512];

  const int rt = blockIdx.x;   // 0..15 row tile
  const int c = blockIdx.y;    // 0..63 channel pair
  const int b = blockIdx.z;    // 0..7
  const int tid = threadIdx.x;

  if (tid < 40) {
    int widx = (tid < 36) ? (tid / 9) : (tid - 36);
    int o = (widx < 2) ? (2 * c + widx) : (128 + 2 * c + widx - 2);
    swb[tid] = (tid < 36) ? w2[o * 9 + tid % 9] : b2[o];
  }

  const int gy0 = rt * 16 - 1;
  const uint4* src0 = (const uint4*)(g_h1 + ((size_t)(b * HID_ + c)) * HW_);
  const uint4* src1 = (const uint4*)(g_h1 + ((size_t)(b * HID_ + 64 + c)) * HW_);
  for (int i = tid; i < 1152; i += 256) {   // 2ch * 18 rows * 32 uint4
    int ch = (i >= 576) ? 1 : 0;
    int j = i - ch * 576;
    int row = j >> 5, k8 = j & 31;
    int gy = gy0 + row;
    uint4 v = make_uint4(0, 0, 0, 0);
    if ((unsigned)gy < 256u) v = (ch ? src1 : src0)[gy * 32 + k8];
    *(uint4*)(&sI[ch][row * 272 + 8 + k8 * 8]) = v;
  }
  if (tid < 72) {  // zero halo cols 7 and 264
    int ch = (tid >= 36) ? 1 : 0;
    int t = tid - ch * 36;
    sI[ch][(t >> 1) * 272 + ((t & 1) ? 264 : 7)] = __float2bfloat16(0.f);
  }
  __syncthreads();

  const int rg = tid >> 6;    // 0..3
  const int cb = tid & 63;    // 0..63
  const int r0 = rg * 4;      // output rows (local) r0..r0+3; smem rows r0..r0+5
  const int sc = 8 + cb * 4;  // first output col in smem coords

  float w0[9], w1v[9], w2v[9], w3v[9];
#pragma unroll
  for (int t = 0; t < 9; t++) {
    w0[t] = swb[t];
    w1v[t] = swb[9 + t];
    w2v[t] = swb[18 + t];
    w3v[t] = swb[27 + t];
  }
  const float bs0 = swb[36], bs1 = swb[37], bs2 = swb[38], bs3 = swb[39];

#define LDROW(ch, row, r)                                                     \
  {                                                                           \
    const __nv_bfloat162* p_ =                                                \
        (const __nv_bfloat162*)(&sI[ch][(row)*272 + sc - 2]);                 \
    float2 q0 = __bfloat1622float2(p_[0]);                                    \
    float2 q1 = __bfloat1622float2(p_[1]);                                    \
    float2 q2 = __bfloat1622float2(p_[2]);                                    \
    float2 q3 = __bfloat1622float2(p_[3]);                                    \
    r[0] = q0.y; r[1] = q1.x; r[2] = q1.y;                                    \
    r[3] = q2.x; r[4] = q2.y; r[5] = q3.x;                                    \
  }

  float A0[6], A1[6], A2[6], B0[6], B1[6], B2[6];
  LDROW(0, r0, A0);
  LDROW(0, r0 + 1, A1);
  LDROW(1, r0, B0);
  LDROW(1, r0 + 1, B1);

  float sum0 = 0.f, sum1 = 0.f;
  size_t obase =
      ((size_t)(b * HID_ + 2 * c)) * HW_ + (size_t)(rt * 16 + r0) * 256 + cb * 4;

#pragma unroll
  for (int orow = 0; orow < 4; orow++) {
    LDROW(0, r0 + orow + 2, A2);
    LDROW(1, r0 + orow + 2, B2);
    float a0[4] = {0, 0, 0, 0}, a1[4] = {0, 0, 0, 0};
    float c0[4] = {0, 0, 0, 0}, c1[4] = {0, 0, 0, 0};
#pragma unroll
    for (int k = 0; k < 4; k++) {
#pragma unroll
      for (int dx = 0; dx < 3; dx++) {
        a0[k] += w0[dx] * A0[k + dx] + w0[3 + dx] * A1[k + dx] + w0[6 + dx] * A2[k + dx];
        a1[k] += w1v[dx] * A0[k + dx] + w1v[3 + dx] * A1[k + dx] + w1v[6 + dx] * A2[k + dx];
        c0[k] += w2v[dx] * B0[k + dx] + w2v[3 + dx] * B1[k + dx] + w2v[6 + dx] * B2[k + dx];
        c1[k] += w3v[dx] * B0[k + dx] + w3v[3 + dx] * B1[k + dx] + w3v[6 + dx] * B2[k + dx];
      }
    }
    alignas(8) __nv_bfloat16 o0[4], o1[4];
#pragma unroll
    for (int k = 0; k < 4; k++) {
      float h0 = (a0[k] + bs0) * (c0[k] + bs2);
      float h1 = (a1[k] + bs1) * (c1[k] + bs3);
      sum0 += h0;
      sum1 += h1;
      o0[k] = __float2bfloat16(h0);
      o1[k] = __float2bfloat16(h1);
    }
    *(uint2*)&g_h2[obase + (size_t)orow * 256] = *(const uint2*)o0;
    *(uint2*)&g_h2[obase + HW_ + (size_t)orow * 256] = *(const uint2*)o1;
#pragma unroll
    for (int t = 0; t < 6; t++) {
      A0[t] = A1[t]; A1[t] = A2[t];
      B0[t] = B1[t]; B1[t] = B2[t];
    }
  }
#undef LDROW

  // deterministic per-tile pool partials
  sred[tid] = sum0;
  sred[256 + tid] = sum1;
  __syncthreads();
  for (int s = 128; s > 0; s >>= 1) {
    if (tid < s) {
      sred[tid] += sred[tid + s];
      sred[256 + tid] += sred[256 + tid + s];
    }
    __syncthreads();
  }
  if (tid == 0) {
    g_pool_part[(b * HID_ + 2 * c) * 16 + rt] = sred[0];
    g_pool_part[(b * HID_ + 2 * c + 1) * 16 + rt] = sred[256];
  }
}

// ---------------------------------------------------------------------------
// K3: attention matvec: attn[b][o] = b_sca[o] + sum_c w_sca[o][c]*mean_pool[b][c]
// ---------------------------------------------------------------------------
__global__ void k3_attn(const float* __restrict__ w_sca,
                        const float* __restrict__ b_sca) {
  __shared__ float sp[HID_];
  int b = blockIdx.x;
  int o = threadIdx.x;
  float s = 0.f;
  const float* pp = g_pool_part + (b * HID_ + o) * 16;
#pragma unroll
  for (int t = 0; t < 16; t++) s += pp[t];
  sp[o] = s * (1.f / 65536.f);
  __syncthreads();
  float acc = b_sca[o];
  const float* w = w_sca + o * HID_;
#pragma unroll 8
  for (int cc = 0; cc < HID_; cc++) acc += w[cc] * sp[cc];
  g_attn[b * HID_ + o] = acc;
}

// ---------------------------------------------------------------------------
// K4: (h2*attn) @ w3^T + b3, out = x + beta*h3. attn folded into weights.
// Block: 128 pixels x 64 out-channels, K=128. 256 threads (8 warps: 2M x 4N)
// Strides padded to 136 (68 words) for conflict-free mma operand loads.
// ---------------------------------------------------------------------------
#define K4_OFF_A 0       // h2 bf16 [128 px][136]   = 34816 B
#define K4_OFF_W 34816   // w3*attn bf16 [64][136]  = 17408 B
#define K4_OFF_AT 52224  // attn f32 [128]          =   512 B
#define K4_OFF_O 52736   // out stage f32 [64][132] = 33792 B
#define K4_SMEM 86528

__global__ void __launch_bounds__(256)
k4_gemm_residual(const float* __restrict__ w3, const float* __restrict__ b3,
                 const float* __restrict__ beta, const float* __restrict__ x,
                 float* __restrict__ out) {
  extern __shared__ char sm4[];
  __nv_bfloat16* sA = (__nv_bfloat16*)(sm4 + K4_OFF_A);
  __nv_bfloat16* sWB = (__nv_bfloat16*)(sm4 + K4_OFF_W);
  float* sAt = (float*)(sm4 + K4_OFF_AT);
  float* sO = (float*)(sm4 + K4_OFF_O);

  const int tid = threadIdx.x;
  const int b = blockIdx.x >> 9;
  const int pix0 = (blockIdx.x & 511) << 7;

  if (tid < 128) sAt[tid] = g_attn[b * HID_ + tid];

  // load h2 tile (uint2 = 4 px) with transpose -> sA[pixel][ch]
  const uint2* h2u2 = (const uint2*)g_h2;
  size_t base2 = (((size_t)b * HID_) * HW_ + pix0) >> 2;
  for (int i = tid; i < 128 * 32; i += 256) {
    int ch = i >> 5, j2 = i & 31;
    uint2 uv = h2u2[base2 + (size_t)ch * (HW_ / 4) + j2];
    __nv_bfloat162 v0 = *(__nv_bfloat162*)&uv.x;
    __nv_bfloat162 v1 = *(__nv_bfloat162*)&uv.y;
    int px = 4 * j2;
    sA[(px + 0) * 136 + ch] = v0.x;
    sA[(px + 1) * 136 + ch] = v0.y;
    sA[(px + 2) * 136 + ch] = v1.x;
    sA[(px + 3) * 136 + ch] = v1.y;
  }
  __syncthreads();  // sAt + sA ready
  for (int i = tid; i < 64 * 128; i += 256) {
    int o = i >> 7, k = i & 127;
    sWB[o * 136 + k] = __float2bfloat16(w3[i] * sAt[k]);
  }
  __syncthreads();

  const int lane = tid & 31, wid = tid >> 5;
  const int lr = lane >> 2, lc = lane & 3;
  const int MB = (wid & 1) * 32;    // out-channel tile
  const int NBp = (wid >> 1) * 32;  // pixel tile

  float acc[2][4][4];
#pragma unroll
  for (int mt = 0; mt < 2; mt++)
#pragma unroll
    for (int nt = 0; nt < 4; nt++)
#pragma unroll
      for (int r = 0; r < 4; r++) acc[mt][nt][r] = 0.f;

#pragma unroll
  for (int ks = 0; ks < 8; ks++) {
    int ca = ks * 16 + lc * 2;
    unsigned a[2][4];
#pragma unroll
    for (int mt = 0; mt < 2; mt++) {
      int r0 = MB + mt * 16 + lr;
      a[mt][0] = ldu(&sWB[r0 * 136 + ca]);
      a[mt][1] = ldu(&sWB[(r0 + 8) * 136 + ca]);
      a[mt][2] = ldu(&sWB[r0 * 136 + ca + 8]);
      a[mt][3] = ldu(&sWB[(r0 + 8) * 136 + ca + 8]);
    }
#pragma unroll
    for (int nt = 0; nt < 4; nt++) {
      int n = NBp + nt * 8 + lr;
      unsigned b0 = ldu(&sA[n * 136 + ca]);
      unsigned b1r = ldu(&sA[n * 136 + ca + 8]);
      MMA_BF16(acc[0][nt], a[0], b0, b1r);
      MMA_BF16(acc[1][nt], a[1], b0, b1r);
    }
  }

#pragma unroll
  for (int mt = 0; mt < 2; mt++)
#pragma unroll
    for (int nt = 0; nt < 4; nt++)
#pragma unroll
      for (int r = 0; r < 4; r++) {
        int row = MB + mt * 16 + lr + ((r & 2) ? 8 : 0);
        int col = NBp + nt * 8 + lc * 2 + (r & 1);
        sO[row * 132 + col] = acc[mt][nt][r];
      }
  __syncthreads();

  // residual + beta, float4 vectorized
  size_t xbase = ((size_t)b * C_) * HW_ + pix0;
  for (int i = tid; i < 64 * 32; i += 256) {
    int o = i >> 5, p4 = (i & 31) * 4;
    float4 hv = *(const float4*)&sO[o * 132 + p4];
    size_t idx = xbase + (size_t)o * HW_ + p4;
    float4 xin = *(const float4*)&x[idx];
    float bb = b3[o], be = beta[o];
    float4 r;
    r.x = xin.x + (hv.x + bb) * be;
    r.y = xin.y + (hv.y + bb) * be;
    r.z = xin.z + (hv.z + bb) * be;
    r.w = xin.w + (hv.w + bb) * be;
    *(float4*)&out[idx] = r;
  }
}

// ---------------------------------------------------------------------------
extern "C" void kernel_launch(void* const* d_in, const int* in_sizes, int n_in,
                              void* d_out, int out_size) {
  const float* x = (const float*)d_in[0];
  const float* ln_w = (const float*)d_in[1];
  const float* ln_b = (const float*)d_in[2];
  const float* w1 = (const float*)d_in[3];
  const float* b1 = (const float*)d_in[4];
  const float* w2 = (const float*)d_in[5];
  const float* b2 = (const float*)d_in[6];
  const float* w_sca = (const float*)d_in[7];
  const float* b_sca = (const float*)d_in[8];
  const float* w3 = (const float*)d_in[9];
  const float* b3 = (const float*)d_in[10];
  const float* beta = (const float*)d_in[11];
  float* out = (float*)d_out;

  cudaFuncSetAttribute(k1_ln_gemm_gate,
                       cudaFuncAttributeMaxDynamicSharedMemorySize, K1_SMEM);
  cudaFuncSetAttribute(k4_gemm_residual,
                       cudaFuncAttributeMaxDynamicSharedMemorySize, K4_SMEM);

  k1_ln_gemm_gate<<<4096, 512, K1_SMEM>>>(x, ln_w, ln_b, w1, b1);
  k2_dwconv_gate_pool<<<dim3(16, 64, 8), 256>>>(w2, b2);
  k3_attn<<<8, 128>>>(w_sca, b_sca);
  k4_gemm_residual<<<4096, 256, K4_SMEM>>>(w3, b3, beta, x, out);
}

// round 5
// speedup vs baseline: 1.7815x; 1.3430x over previous
#include <cuda_runtime.h>
#include <cuda_bf16.h>
#include <cstdint>

#define NB_ 8
#define C_ 64
#define HID_ 128
#define HW_ 65536

// Scratch (device globals; no allocation in kernel_launch)
__device__ __nv_bfloat16 g_h1[(size_t)NB_ * HID_ * HW_];
__device__ __nv_bfloat16 g_h2[(size_t)NB_ * HID_ * HW_];
__device__ float g_pool_part[NB_ * HID_ * 16];
__device__ float g_attn[NB_ * HID_];

#define MMA_BF16(d, A, b0r, b1r)                                              \
  asm volatile(                                                               \
      "mma.sync.aligned.m16n8k16.row.col.f32.bf16.bf16.f32 "                  \
      "{%0,%1,%2,%3},{%4,%5,%6,%7},{%8,%9},{%0,%1,%2,%3};\n"                  \
      : "+f"((d)[0]), "+f"((d)[1]), "+f"((d)[2]), "+f"((d)[3])                \
      : "r"((A)[0]), "r"((A)[1]), "r"((A)[2]), "r"((A)[3]), "r"(b0r),         \
        "r"(b1r))

__device__ __forceinline__ unsigned ldu(const __nv_bfloat16* p) {
  return *reinterpret_cast<const unsigned*>(p);
}

__device__ __forceinline__ void ldsm_trans(unsigned (&r)[4],
                                           const __nv_bfloat16* p) {
  unsigned addr = (unsigned)__cvta_generic_to_shared(p);
  asm volatile(
      "ldmatrix.sync.aligned.m8n8.x4.trans.shared.b16 {%0,%1,%2,%3}, [%4];"
      : "=r"(r[0]), "=r"(r[1]), "=r"(r[2]), "=r"(r[3])
      : "r"(addr));
}

// ---------------------------------------------------------------------------
// K1: LayerNorm + 1x1 conv (64->256, bf16 mma) + SimpleGate -> g_h1 (bf16)
// Block: 128 pixels, 512 threads (16 warps as 4M x 4N-pairhalves)
// ---------------------------------------------------------------------------
#define K1_OFF_W 0          // w1 bf16 [256][72]          = 36864 B
#define K1_OFF_A 36864      // xn bf16 [128][72]          = 18432 B
#define K1_OFF_B1 55296     // b1 f32  [256]              =  1024 B
#define K1_OFF_RED 56320    // LN partials f32 [1024]     =  4096 B
#define K1_OFF_H 60416      // h1 stage bf16 [128][132]   = 33792 B
#define K1_SMEM 94208

__global__ void __launch_bounds__(512, 1)
k1_ln_gemm_gate(const float* __restrict__ x, const float* __restrict__ ln_w,
                const float* __restrict__ ln_b, const float* __restrict__ w1,
                const float* __restrict__ b1) {
  extern __shared__ char sm1[];
  __nv_bfloat16* sW = (__nv_bfloat16*)(sm1 + K1_OFF_W);
  __nv_bfloat16* sA = (__nv_bfloat16*)(sm1 + K1_OFF_A);
  float* sB1 = (float*)(sm1 + K1_OFF_B1);
  float* sRED = (float*)(sm1 + K1_OFF_RED);
  __nv_bfloat16* sH = (__nv_bfloat16*)(sm1 + K1_OFF_H);

  const int tid = threadIdx.x;
  const int b = blockIdx.x >> 9;               // 512 blocks per image
  const int pix0 = (blockIdx.x & 511) << 7;    // 128 pixels per block

  // weights -> smem (bf16)
  for (int i = tid; i < 256 * 64; i += 512)
    sW[(i >> 6) * 72 + (i & 63)] = __float2bfloat16(w1[i]);
  if (tid < 256) sB1[tid] = b1[tid];

  // load x tile + LayerNorm (4 threads per pixel, 16 channels each)
  const int p = tid & 127, q = tid >> 7;
  const float* xb = x + (size_t)b * C_ * HW_ + (size_t)(q * 16) * HW_ + pix0 + p;
  float v[16], s1 = 0.f, s2 = 0.f;
#pragma unroll
  for (int i = 0; i < 16; i++) {
    float t = xb[(size_t)i * HW_];
    v[i] = t;
    s1 += t;
    s2 += t * t;
  }
  sRED[tid] = s1;
  sRED[512 + tid] = s2;
  __syncthreads();
  float t1 = sRED[p] + sRED[128 + p] + sRED[256 + p] + sRED[384 + p];
  float t2 = sRED[512 + p] + sRED[640 + p] + sRED[768 + p] + sRED[896 + p];
  float mean = t1 * (1.f / 64.f);
  float var = t2 * (1.f / 64.f) - mean * mean;
  float rstd = rsqrtf(var + 1e-6f);
#pragma unroll
  for (int i = 0; i < 16; i++) {
    int c = q * 16 + i;
    float xn = (v[i] - mean) * rstd * ln_w[c] + ln_b[c];
    sA[p * 72 + c] = __float2bfloat16(xn);
  }
  __syncthreads();

  // mma: block tile M=128px, Npair=128 (both gate halves). warp M=32, Npair=32
  const int lane = tid & 31, wid = tid >> 5;
  const int lr = lane >> 2, lc = lane & 3;
  const int MB = (wid & 3) * 32;
  const int NBc = (wid >> 2) * 32;

  float acc1[2][4][4], acc2[2][4][4];
#pragma unroll
  for (int mt = 0; mt < 2; mt++)
#pragma unroll
    for (int nt = 0; nt < 4; nt++)
#pragma unroll
      for (int r = 0; r < 4; r++) {
        acc1[mt][nt][r] = 0.f;
        acc2[mt][nt][r] = 0.f;
      }

#pragma unroll
  for (int ks = 0; ks < 4; ks++) {
    const int ca = ks * 16 + lc * 2;
    unsigned a[2][4];
#pragma unroll
    for (int mt = 0; mt < 2; mt++) {
      int r0 = MB + mt * 16 + lr;
      a[mt][0] = ldu(&sA[r0 * 72 + ca]);
      a[mt][1] = ldu(&sA[(r0 + 8) * 72 + ca]);
      a[mt][2] = ldu(&sA[r0 * 72 + ca + 8]);
      a[mt][3] = ldu(&sA[(r0 + 8) * 72 + ca + 8]);
    }
#pragma unroll
    for (int nt = 0; nt < 4; nt++) {
      int n1 = NBc + nt * 8 + lr;
      unsigned b0 = ldu(&sW[n1 * 72 + ca]);
      unsigned b1r = ldu(&sW[n1 * 72 + ca + 8]);
      MMA_BF16(acc1[0][nt], a[0], b0, b1r);
      MMA_BF16(acc1[1][nt], a[1], b0, b1r);
      int n2 = n1 + 128;
      unsigned c0 = ldu(&sW[n2 * 72 + ca]);
      unsigned c1r = ldu(&sW[n2 * 72 + ca + 8]);
      MMA_BF16(acc2[0][nt], a[0], c0, c1r);
      MMA_BF16(acc2[1][nt], a[1], c0, c1r);
    }
  }

  // gate in-register, stage [ch][pixel] in smem
#pragma unroll
  for (int mt = 0; mt < 2; mt++)
#pragma unroll
    for (int nt = 0; nt < 4; nt++)
#pragma unroll
      for (int r = 0; r < 4; r++) {
        int row = MB + mt * 16 + lr + ((r & 2) ? 8 : 0);
        int col = NBc + nt * 8 + lc * 2 + (r & 1);
        float y1 = acc1[mt][nt][r] + sB1[col];
        float y2 = acc2[mt][nt][r] + sB1[col + 128];
        sH[col * 132 + row] = __float2bfloat16(y1 * y2);
      }
  __syncthreads();

  // coalesced write-out (uint2 = 4 pixels)
  const uint2* sH2 = (const uint2*)sH;            // stride 33 uint2/row
  uint2* out2 = (uint2*)g_h1;
  size_t base2 = (((size_t)b * HID_) * HW_ + pix0) >> 2;
  for (int i = tid; i < 128 * 32; i += 512) {
    int ch = i >> 5, j2 = i & 31;
    out2[base2 + (size_t)ch * (HW_ / 4) + j2] = sH2[ch * 33 + j2];
  }
}

// ---------------------------------------------------------------------------
// K2: grouped 3x3 depthwise (2 out per group) + gate + pool partials
// Full-width row tiles: 256 wide x 16 high; halo only in y (x-halo = border 0).
// 256 threads: thread = 4x4 output micro-tile, register row sliding.
// ---------------------------------------------------------------------------
__global__ void __launch_bounds__(256)
k2_dwconv_gate_pool(const float* __restrict__ w2, const float* __restrict__ b2) {
  __shared__ __nv_bfloat16 sI[2][18 * 272];  // data at cols 8..263, row 16B-aligned
  __shared__ float swb[40];
  __shared__ float sred[512];

  const int rt = blockIdx.x;   // 0..15 row tile
  const int c = blockIdx.y;    // 0..63 channel pair
  const int b = blockIdx.z;    // 0..7
  const int tid = threadIdx.x;

  if (tid < 40) {
    int widx = (tid < 36) ? (tid / 9) : (tid - 36);
    int o = (widx < 2) ? (2 * c + widx) : (128 + 2 * c + widx - 2);
    swb[tid] = (tid < 36) ? w2[o * 9 + tid % 9] : b2[o];
  }

  const int gy0 = rt * 16 - 1;
  const uint4* src0 = (const uint4*)(g_h1 + ((size_t)(b * HID_ + c)) * HW_);
  const uint4* src1 = (const uint4*)(g_h1 + ((size_t)(b * HID_ + 64 + c)) * HW_);
  for (int i = tid; i < 1152; i += 256) {   // 2ch * 18 rows * 32 uint4
    int ch = (i >= 576) ? 1 : 0;
    int j = i - ch * 576;
    int row = j >> 5, k8 = j & 31;
    int gy = gy0 + row;
    uint4 v = make_uint4(0, 0, 0, 0);
    if ((unsigned)gy < 256u) v = (ch ? src1 : src0)[gy * 32 + k8];
    *(uint4*)(&sI[ch][row * 272 + 8 + k8 * 8]) = v;
  }
  if (tid < 72) {  // zero halo cols 7 and 264
    int ch = (tid >= 36) ? 1 : 0;
    int t = tid - ch * 36;
    sI[ch][(t >> 1) * 272 + ((t & 1) ? 264 : 7)] = __float2bfloat16(0.f);
  }
  __syncthreads();

  const int rg = tid >> 6;    // 0..3
  const int cb = tid & 63;    // 0..63
  const int r0 = rg * 4;      // output rows (local) r0..r0+3; smem rows r0..r0+5
  const int sc = 8 + cb * 4;  // first output col in smem coords

  float w0[9], w1v[9], w2v[9], w3v[9];
#pragma unroll
  for (int t = 0; t < 9; t++) {
    w0[t] = swb[t];
    w1v[t] = swb[9 + t];
    w2v[t] = swb[18 + t];
    w3v[t] = swb[27 + t];
  }
  const float bs0 = swb[36], bs1 = swb[37], bs2 = swb[38], bs3 = swb[39];

#define LDROW(ch, row, r)                                                     \
  {                                                                           \
    const __nv_bfloat162* p_ =                                                \
        (const __nv_bfloat162*)(&sI[ch][(row)*272 + sc - 2]);                 \
    float2 q0 = __bfloat1622float2(p_[0]);                                    \
    float2 q1 = __bfloat1622float2(p_[1]);                                    \
    float2 q2 = __bfloat1622float2(p_[2]);                                    \
    float2 q3 = __bfloat1622float2(p_[3]);                                    \
    r[0] = q0.y; r[1] = q1.x; r[2] = q1.y;                                    \
    r[3] = q2.x; r[4] = q2.y; r[5] = q3.x;                                    \
  }

  float A0[6], A1[6], A2[6], B0[6], B1[6], B2[6];
  LDROW(0, r0, A0);
  LDROW(0, r0 + 1, A1);
  LDROW(1, r0, B0);
  LDROW(1, r0 + 1, B1);

  float sum0 = 0.f, sum1 = 0.f;
  size_t obase =
      ((size_t)(b * HID_ + 2 * c)) * HW_ + (size_t)(rt * 16 + r0) * 256 + cb * 4;

#pragma unroll
  for (int orow = 0; orow < 4; orow++) {
    LDROW(0, r0 + orow + 2, A2);
    LDROW(1, r0 + orow + 2, B2);
    float a0[4] = {0, 0, 0, 0}, a1[4] = {0, 0, 0, 0};
    float c0[4] = {0, 0, 0, 0}, c1[4] = {0, 0, 0, 0};
#pragma unroll
    for (int k = 0; k < 4; k++) {
#pragma unroll
      for (int dx = 0; dx < 3; dx++) {
        a0[k] += w0[dx] * A0[k + dx] + w0[3 + dx] * A1[k + dx] + w0[6 + dx] * A2[k + dx];
        a1[k] += w1v[dx] * A0[k + dx] + w1v[3 + dx] * A1[k + dx] + w1v[6 + dx] * A2[k + dx];
        c0[k] += w2v[dx] * B0[k + dx] + w2v[3 + dx] * B1[k + dx] + w2v[6 + dx] * B2[k + dx];
        c1[k] += w3v[dx] * B0[k + dx] + w3v[3 + dx] * B1[k + dx] + w3v[6 + dx] * B2[k + dx];
      }
    }
    alignas(8) __nv_bfloat16 o0[4], o1[4];
#pragma unroll
    for (int k = 0; k < 4; k++) {
      float h0 = (a0[k] + bs0) * (c0[k] + bs2);
      float h1 = (a1[k] + bs1) * (c1[k] + bs3);
      sum0 += h0;
      sum1 += h1;
      o0[k] = __float2bfloat16(h0);
      o1[k] = __float2bfloat16(h1);
    }
    *(uint2*)&g_h2[obase + (size_t)orow * 256] = *(const uint2*)o0;
    *(uint2*)&g_h2[obase + HW_ + (size_t)orow * 256] = *(const uint2*)o1;
#pragma unroll
    for (int t = 0; t < 6; t++) {
      A0[t] = A1[t]; A1[t] = A2[t];
      B0[t] = B1[t]; B1[t] = B2[t];
    }
  }
#undef LDROW

  // deterministic per-tile pool partials
  sred[tid] = sum0;
  sred[256 + tid] = sum1;
  __syncthreads();
  for (int s = 128; s > 0; s >>= 1) {
    if (tid < s) {
      sred[tid] += sred[tid + s];
      sred[256 + tid] += sred[256 + tid + s];
    }
    __syncthreads();
  }
  if (tid == 0) {
    g_pool_part[(b * HID_ + 2 * c) * 16 + rt] = sred[0];
    g_pool_part[(b * HID_ + 2 * c + 1) * 16 + rt] = sred[256];
  }
}

// ---------------------------------------------------------------------------
// K3: attention matvec: attn[b][o] = b_sca[o] + sum_c w_sca[o][c]*mean_pool[b][c]
// ---------------------------------------------------------------------------
__global__ void k3_attn(const float* __restrict__ w_sca,
                        const float* __restrict__ b_sca) {
  __shared__ float sp[HID_];
  int b = blockIdx.x;
  int o = threadIdx.x;
  float s = 0.f;
  const float* pp = g_pool_part + (b * HID_ + o) * 16;
#pragma unroll
  for (int t = 0; t < 16; t++) s += pp[t];
  sp[o] = s * (1.f / 65536.f);
  __syncthreads();
  float acc = b_sca[o];
  const float* w = w_sca + o * HID_;
#pragma unroll 8
  for (int cc = 0; cc < HID_; cc++) acc += w[cc] * sp[cc];
  g_attn[b * HID_ + o] = acc;
}

// ---------------------------------------------------------------------------
// K4: (h2*attn) @ w3^T + b3, out = x + beta*h3. attn folded into weights.
// h2 tile kept in NATIVE [ch][px] layout (coalesced uint4 copy, no transpose);
// A-fragments loaded via ldmatrix.x4.trans (HW transpose, conflict-free).
// sO (f32 output stage) aliases the sA region -> 52.7KB smem, 4 blocks/SM.
// 256 threads (8 warps: 4 Mpx x 2 Ncout).
// ---------------------------------------------------------------------------
#define K4_OFF_A 0       // h2 bf16 [128 ch][136]   = 34816 B (sO f32[64][132] aliases)
#define K4_OFF_W 34816   // w3*attn bf16 [64][136]  = 17408 B
#define K4_OFF_AT 52224  // attn f32 [128]          =   512 B
#define K4_SMEM 52736

__global__ void __launch_bounds__(256)
k4_gemm_residual(const float* __restrict__ w3, const float* __restrict__ b3,
                 const float* __restrict__ beta, const float* __restrict__ x,
                 float* __restrict__ out) {
  extern __shared__ char sm4[];
  __nv_bfloat16* sA = (__nv_bfloat16*)(sm4 + K4_OFF_A);   // [128 ch][136]
  __nv_bfloat16* sWB = (__nv_bfloat16*)(sm4 + K4_OFF_W);  // [64 cout][136]
  float* sAt = (float*)(sm4 + K4_OFF_AT);
  float* sO = (float*)(sm4 + K4_OFF_A);                   // aliases sA

  const int tid = threadIdx.x;
  const int b = blockIdx.x >> 9;
  const int pix0 = (blockIdx.x & 511) << 7;

  if (tid < 128) sAt[tid] = g_attn[b * HID_ + tid];

  // h2 tile, native [ch][px]: pure coalesced uint4 copy (no transpose)
  const uint4* h2v = (const uint4*)g_h2;
  uint4* sA4 = (uint4*)sA;  // 17 uint4 per row (136 bf16)
  size_t base8 = (((size_t)b * HID_) * HW_ + pix0) >> 3;
  for (int i = tid; i < 128 * 16; i += 256) {
    int ch = i >> 4, q = i & 15;
    sA4[ch * 17 + q] = h2v[base8 + (size_t)ch * (HW_ / 8) + q];
  }
  __syncthreads();  // sAt + sA ready
  for (int i = tid; i < 64 * 128; i += 256) {
    int o = i >> 7, k = i & 127;
    sWB[o * 136 + k] = __float2bfloat16(w3[i] * sAt[k]);
  }
  __syncthreads();

  const int lane = tid & 31, wid = tid >> 5;
  const int lr = lane >> 2, lc = lane & 3;
  const int MB = (wid & 3) * 32;    // pixel tile (M)
  const int NBc = (wid >> 2) * 32;  // cout tile (N)

  // per-lane ldmatrix row/col selectors (constant across k-iters)
  const int lkoff = ((lane >> 4) << 3) + (lane & 7);  // +0..7 (+8 for grp hi)
  const int lmoff = ((lane >> 3) & 1) << 3;           // 0 or 8

  float acc[2][4][4];
#pragma unroll
  for (int mt = 0; mt < 2; mt++)
#pragma unroll
    for (int nt = 0; nt < 4; nt++)
#pragma unroll
      for (int r = 0; r < 4; r++) acc[mt][nt][r] = 0.f;

#pragma unroll
  for (int ks = 0; ks < 8; ks++) {
    const int k0 = ks * 16;
    const int krow = k0 + lkoff;
    unsigned a[2][4];
#pragma unroll
    for (int mt = 0; mt < 2; mt++)
      ldsm_trans(a[mt], &sA[krow * 136 + MB + mt * 16 + lmoff]);
    const int ca = k0 + lc * 2;
#pragma unroll
    for (int nt = 0; nt < 4; nt++) {
      int n = NBc + nt * 8 + lr;
      unsigned b0 = ldu(&sWB[n * 136 + ca]);
      unsigned b1r = ldu(&sWB[n * 136 + ca + 8]);
      MMA_BF16(acc[0][nt], a[0], b0, b1r);
      MMA_BF16(acc[1][nt], a[1], b0, b1r);
    }
  }

  __syncthreads();  // all reads of sA done before aliasing as sO

  // stage D[px][cout] -> sO[cout][132px] (banks 8*lc+lr: conflict-free)
#pragma unroll
  for (int mt = 0; mt < 2; mt++)
#pragma unroll
    for (int nt = 0; nt < 4; nt++)
#pragma unroll
      for (int r = 0; r < 4; r++) {
        int row = MB + mt * 16 + lr + ((r & 2) ? 8 : 0);      // px
        int col = NBc + nt * 8 + lc * 2 + (r & 1);            // cout
        sO[col * 132 + row] = acc[mt][nt][r];
      }
  __syncthreads();

  // residual + beta, float4 vectorized
  size_t xbase = ((size_t)b * C_) * HW_ + pix0;
  for (int i = tid; i < 64 * 32; i += 256) {
    int o = i >> 5, p4 = (i & 31) * 4;
    float4 hv = *(const float4*)&sO[o * 132 + p4];
    size_t idx = xbase + (size_t)o * HW_ + p4;
    float4 xin = *(const float4*)&x[idx];
    float bb = b3[o], be = beta[o];
    float4 r;
    r.x = xin.x + (hv.x + bb) * be;
    r.y = xin.y + (hv.y + bb) * be;
    r.z = xin.z + (hv.z + bb) * be;
    r.w = xin.w + (hv.w + bb) * be;
    *(float4*)&out[idx] = r;
  }
}

// ---------------------------------------------------------------------------
extern "C" void kernel_launch(void* const* d_in, const int* in_sizes, int n_in,
                              void* d_out, int out_size) {
  const float* x = (const float*)d_in[0];
  const float* ln_w = (const float*)d_in[1];
  const float* ln_b = (const float*)d_in[2];
  const float* w1 = (const float*)d_in[3];
  const float* b1 = (const float*)d_in[4];
  const float* w2 = (const float*)d_in[5];
  const float* b2 = (const float*)d_in[6];
  const float* w_sca = (const float*)d_in[7];
  const float* b_sca = (const float*)d_in[8];
  const float* w3 = (const float*)d_in[9];
  const float* b3 = (const float*)d_in[10];
  const float* beta = (const float*)d_in[11];
  float* out = (float*)d_out;

  cudaFuncSetAttribute(k1_ln_gemm_gate,
                       cudaFuncAttributeMaxDynamicSharedMemorySize, K1_SMEM);
  cudaFuncSetAttribute(k4_gemm_residual,
                       cudaFuncAttributeMaxDynamicSharedMemorySize, K4_SMEM);

  k1_ln_gemm_gate<<<4096, 512, K1_SMEM>>>(x, ln_w, ln_b, w1, b1);
  k2_dwconv_gate_pool<<<dim3(16, 64, 8), 256>>>(w2, b2);
  k3_attn<<<8, 128>>>(w_sca, b_sca);
  k4_gemm_residual<<<4096, 256, K4_SMEM>>>(w3, b3, beta, x, out);
}

// round 7
// speedup vs baseline: 1.8449x; 1.0356x over previous
#include <cuda_runtime.h>
#include <cuda_bf16.h>
#include <cstdint>

#define NB_ 8
#define C_ 64
#define HID_ 128
#define HW_ 65536

// Scratch (device globals; no allocation in kernel_launch)
__device__ __nv_bfloat16 g_h1[(size_t)NB_ * HID_ * HW_];
__device__ __nv_bfloat16 g_h2[(size_t)NB_ * HID_ * HW_];
__device__ float g_pool_part[NB_ * HID_ * 16];
__device__ __nv_bfloat16 g_w1bf[256 * 64];          // prepped bf16 w1
__device__ __nv_bfloat16 g_wbf[NB_ * 64 * HID_];    // per-batch bf16 w3*attn

#define MMA_BF16(d, A, b0r, b1r)                                              \
  asm volatile(                                                               \
      "mma.sync.aligned.m16n8k16.row.col.f32.bf16.bf16.f32 "                  \
      "{%0,%1,%2,%3},{%4,%5,%6,%7},{%8,%9},{%0,%1,%2,%3};\n"                  \
      : "+f"((d)[0]), "+f"((d)[1]), "+f"((d)[2]), "+f"((d)[3])                \
      : "r"((A)[0]), "r"((A)[1]), "r"((A)[2]), "r"((A)[3]), "r"(b0r),         \
        "r"(b1r))

__device__ __forceinline__ void ldsm(unsigned (&r)[4], const __nv_bfloat16* p) {
  unsigned addr = (unsigned)__cvta_generic_to_shared(p);
  asm volatile(
      "ldmatrix.sync.aligned.m8n8.x4.shared.b16 {%0,%1,%2,%3}, [%4];"
      : "=r"(r[0]), "=r"(r[1]), "=r"(r[2]), "=r"(r[3])
      : "r"(addr));
}

__device__ __forceinline__ void ldsm_trans(unsigned (&r)[4],
                                           const __nv_bfloat16* p) {
  unsigned addr = (unsigned)__cvta_generic_to_shared(p);
  asm volatile(
      "ldmatrix.sync.aligned.m8n8.x4.trans.shared.b16 {%0,%1,%2,%3}, [%4];"
      : "=r"(r[0]), "=r"(r[1]), "=r"(r[2]), "=r"(r[3])
      : "r"(addr));
}

// ---------------------------------------------------------------------------
// K0: one-time prep: w1 -> bf16
// ---------------------------------------------------------------------------
__global__ void k0_prep(const float* __restrict__ w1) {
  int i = blockIdx.x * 256 + threadIdx.x;  // 64 blocks x 256 = 16384
  g_w1bf[i] = __float2bfloat16(w1[i]);
}

// ---------------------------------------------------------------------------
// K1: LayerNorm + 1x1 conv (64->256, bf16 mma) + SimpleGate -> g_h1 (bf16)
// Block: 128 pixels, 512 threads. Operand loads via ldmatrix.
// ---------------------------------------------------------------------------
#define K1_OFF_W 0          // w1 bf16 [256][72]          = 36864 B
#define K1_OFF_A 36864      // xn bf16 [128][72]          = 18432 B
#define K1_OFF_B1 55296     // b1 f32  [256]              =  1024 B
#define K1_OFF_RED 56320    // LN partials f32 [1024]     =  4096 B
#define K1_OFF_H 60416      // h1 stage bf16 [128][132]   = 33792 B
#define K1_SMEM 94208

__global__ void __launch_bounds__(512, 1)
k1_ln_gemm_gate(const float* __restrict__ x, const float* __restrict__ ln_w,
                const float* __restrict__ ln_b, const float* __restrict__ b1) {
  extern __shared__ char sm1[];
  __nv_bfloat16* sW = (__nv_bfloat16*)(sm1 + K1_OFF_W);
  __nv_bfloat16* sA = (__nv_bfloat16*)(sm1 + K1_OFF_A);
  float* sB1 = (float*)(sm1 + K1_OFF_B1);
  float* sRED = (float*)(sm1 + K1_OFF_RED);
  __nv_bfloat16* sH = (__nv_bfloat16*)(sm1 + K1_OFF_H);

  const int tid = threadIdx.x;
  const int b = blockIdx.x >> 9;               // 512 blocks per image
  const int pix0 = (blockIdx.x & 511) << 7;    // 128 pixels per block

  // weights -> smem (uint4 copy of prepped bf16)
  {
    const uint4* wsrc = (const uint4*)g_w1bf;  // [256][8 uint4]
    uint4* sW4 = (uint4*)sW;                   // stride 9 uint4 (72 bf16)
    for (int i = tid; i < 2048; i += 512) {
      int rr = i >> 3, q = i & 7;
      sW4[rr * 9 + q] = wsrc[i];
    }
  }
  if (tid < 256) sB1[tid] = b1[tid];

  // load x tile + LayerNorm (4 threads per pixel, 16 channels each)
  const int p = tid & 127, q = tid >> 7;
  const float* xb = x + (size_t)b * C_ * HW_ + (size_t)(q * 16) * HW_ + pix0 + p;
  float v[16], s1 = 0.f, s2 = 0.f;
#pragma unroll
  for (int i = 0; i < 16; i++) {
    float t = xb[(size_t)i * HW_];
    v[i] = t;
    s1 += t;
    s2 += t * t;
  }
  sRED[tid] = s1;
  sRED[512 + tid] = s2;
  __syncthreads();
  float t1 = sRED[p] + sRED[128 + p] + sRED[256 + p] + sRED[384 + p];
  float t2 = sRED[512 + p] + sRED[640 + p] + sRED[768 + p] + sRED[896 + p];
  float mean = t1 * (1.f / 64.f);
  float var = t2 * (1.f / 64.f) - mean * mean;
  float rstd = rsqrtf(var + 1e-6f);
#pragma unroll
  for (int i = 0; i < 16; i++) {
    int c = q * 16 + i;
    float xn = (v[i] - mean) * rstd * ln_w[c] + ln_b[c];
    sA[p * 72 + c] = __float2bfloat16(xn);
  }
  __syncthreads();

  // mma: block tile M=128px, Npair=128 (both gate halves). warp M=32, Npair=32
  const int lane = tid & 31, wid = tid >> 5;
  const int lr = lane >> 2, lc = lane & 3;
  const int MB = (wid & 3) * 32;
  const int NBc = (wid >> 2) * 32;
  const int lofs = ((lane >> 3) & 1) * 8 + (lane & 7);  // ldsm row-in-tile
  const int lhi = (lane >> 4) * 8;                      // ldsm k-half

  float acc1[2][4][4], acc2[2][4][4];
#pragma unroll
  for (int mt = 0; mt < 2; mt++)
#pragma unroll
    for (int nt = 0; nt < 4; nt++)
#pragma unroll
      for (int r = 0; r < 4; r++) {
        acc1[mt][nt][r] = 0.f;
        acc2[mt][nt][r] = 0.f;
      }

#pragma unroll
  for (int ks = 0; ks < 4; ks++) {
    const int kc = ks * 16;
    unsigned a[2][4];
    ldsm(a[0], &sA[(MB + lofs) * 72 + kc + lhi]);
    ldsm(a[1], &sA[(MB + 16 + lofs) * 72 + kc + lhi]);
#pragma unroll
    for (int h = 0; h < 4; h++) {
      const int NB0 = NBc + (h & 1) * 16 + ((h & 2) ? 128 : 0);
      unsigned bb[4];
      ldsm(bb, &sW[(NB0 + lofs) * 72 + kc + lhi]);
      float(*acc)[4][4] = (h & 2) ? acc2 : acc1;
      const int nt0 = (h & 1) * 2;
      MMA_BF16(acc[0][nt0], a[0], bb[0], bb[2]);
      MMA_BF16(acc[1][nt0], a[1], bb[0], bb[2]);
      MMA_BF16(acc[0][nt0 + 1], a[0], bb[1], bb[3]);
      MMA_BF16(acc[1][nt0 + 1], a[1], bb[1], bb[3]);
    }
  }

  // gate in-register, stage [ch][pixel] in smem
#pragma unroll
  for (int mt = 0; mt < 2; mt++)
#pragma unroll
    for (int nt = 0; nt < 4; nt++)
#pragma unroll
      for (int r = 0; r < 4; r++) {
        int row = MB + mt * 16 + lr + ((r & 2) ? 8 : 0);
        int col = NBc + nt * 8 + lc * 2 + (r & 1);
        float y1 = acc1[mt][nt][r] + sB1[col];
        float y2 = acc2[mt][nt][r] + sB1[col + 128];
        sH[col * 132 + row] = __float2bfloat16(y1 * y2);
      }
  __syncthreads();

  // coalesced write-out (uint2 = 4 pixels)
  const uint2* sH2 = (const uint2*)sH;            // stride 33 uint2/row
  uint2* out2 = (uint2*)g_h1;
  size_t base2 = (((size_t)b * HID_) * HW_ + pix0) >> 2;
  for (int i = tid; i < 128 * 32; i += 512) {
    int ch = i >> 5, j2 = i & 31;
    out2[base2 + (size_t)ch * (HW_ / 4) + j2] = sH2[ch * 33 + j2];
  }
}

// ---------------------------------------------------------------------------
// K2: grouped 3x3 depthwise (2 out per group) + gate + pool partials
// Full-width row tiles: 256 wide x 16 high; halo only in y.
// ---------------------------------------------------------------------------
__global__ void __launch_bounds__(256)
k2_dwconv_gate_pool(const float* __restrict__ w2, const float* __restrict__ b2) {
  __shared__ __nv_bfloat16 sI[2][18 * 272];  // data at cols 8..263
  __shared__ float swb[40];
  __shared__ float sred[512];

  const int rt = blockIdx.x;   // 0..15 row tile
  const int c = blockIdx.y;    // 0..63 channel pair
  const int b = blockIdx.z;    // 0..7
  const int tid = threadIdx.x;

  if (tid < 40) {
    int widx = (tid < 36) ? (tid / 9) : (tid - 36);
    int o = (widx < 2) ? (2 * c + widx) : (128 + 2 * c + widx - 2);
    swb[tid] = (tid < 36) ? w2[o * 9 + tid % 9] : b2[o];
  }

  const int gy0 = rt * 16 - 1;
  const uint4* src0 = (const uint4*)(g_h1 + ((size_t)(b * HID_ + c)) * HW_);
  const uint4* src1 = (const uint4*)(g_h1 + ((size_t)(b * HID_ + 64 + c)) * HW_);
  for (int i = tid; i < 1152; i += 256) {   // 2ch * 18 rows * 32 uint4
    int ch = (i >= 576) ? 1 : 0;
    int j = i - ch * 576;
    int row = j >> 5, k8 = j & 31;
    int gy = gy0 + row;
    uint4 v = make_uint4(0, 0, 0, 0);
    if ((unsigned)gy < 256u) v = (ch ? src1 : src0)[gy * 32 + k8];
    *(uint4*)(&sI[ch][row * 272 + 8 + k8 * 8]) = v;
  }
  if (tid < 72) {  // zero halo cols 7 and 264
    int ch = (tid >= 36) ? 1 : 0;
    int t = tid - ch * 36;
    sI[ch][(t >> 1) * 272 + ((t & 1) ? 264 : 7)] = __float2bfloat16(0.f);
  }
  __syncthreads();

  const int rg = tid >> 6;    // 0..3
  const int cb = tid & 63;    // 0..63
  const int r0 = rg * 4;
  const int sc = 8 + cb * 4;

  float w0[9], w1v[9], w2v[9], w3v[9];
#pragma unroll
  for (int t = 0; t < 9; t++) {
    w0[t] = swb[t];
    w1v[t] = swb[9 + t];
    w2v[t] = swb[18 + t];
    w3v[t] = swb[27 + t];
  }
  const float bs0 = swb[36], bs1 = swb[37], bs2 = swb[38], bs3 = swb[39];

#define LDROW(ch, row, r)                                                     \
  {                                                                           \
    const __nv_bfloat162* p_ =                                                \
        (const __nv_bfloat162*)(&sI[ch][(row)*272 + sc - 2]);                 \
    float2 q0 = __bfloat1622float2(p_[0]);                                    \
    float2 q1 = __bfloat1622float2(p_[1]);                                    \
    float2 q2 = __bfloat1622float2(p_[2]);                                    \
    float2 q3 = __bfloat1622float2(p_[3]);                                    \
    r[0] = q0.y; r[1] = q1.x; r[2] = q1.y;                                    \
    r[3] = q2.x; r[4] = q2.y; r[5] = q3.x;                                    \
  }

  float A0[6], A1[6], A2[6], B0[6], B1[6], B2[6];
  LDROW(0, r0, A0);
  LDROW(0, r0 + 1, A1);
  LDROW(1, r0, B0);
  LDROW(1, r0 + 1, B1);

  float sum0 = 0.f, sum1 = 0.f;
  size_t obase =
      ((size_t)(b * HID_ + 2 * c)) * HW_ + (size_t)(rt * 16 + r0) * 256 + cb * 4;

#pragma unroll
  for (int orow = 0; orow < 4; orow++) {
    LDROW(0, r0 + orow + 2, A2);
    LDROW(1, r0 + orow + 2, B2);
    float a0[4] = {0, 0, 0, 0}, a1[4] = {0, 0, 0, 0};
    float c0[4] = {0, 0, 0, 0}, c1[4] = {0, 0, 0, 0};
#pragma unroll
    for (int k = 0; k < 4; k++) {
#pragma unroll
      for (int dx = 0; dx < 3; dx++) {
        a0[k] += w0[dx] * A0[k + dx] + w0[3 + dx] * A1[k + dx] + w0[6 + dx] * A2[k + dx];
        a1[k] += w1v[dx] * A0[k + dx] + w1v[3 + dx] * A1[k + dx] + w1v[6 + dx] * A2[k + dx];
        c0[k] += w2v[dx] * B0[k + dx] + w2v[3 + dx] * B1[k + dx] + w2v[6 + dx] * B2[k + dx];
        c1[k] += w3v[dx] * B0[k + dx] + w3v[3 + dx] * B1[k + dx] + w3v[6 + dx] * B2[k + dx];
      }
    }
    alignas(8) __nv_bfloat16 o0[4], o1[4];
#pragma unroll
    for (int k = 0; k < 4; k++) {
      float h0 = (a0[k] + bs0) * (c0[k] + bs2);
      float h1 = (a1[k] + bs1) * (c1[k] + bs3);
      sum0 += h0;
      sum1 += h1;
      o0[k] = __float2bfloat16(h0);
      o1[k] = __float2bfloat16(h1);
    }
    *(uint2*)&g_h2[obase + (size_t)orow * 256] = *(const uint2*)o0;
    *(uint2*)&g_h2[obase + HW_ + (size_t)orow * 256] = *(const uint2*)o1;
#pragma unroll
    for (int t = 0; t < 6; t++) {
      A0[t] = A1[t]; A1[t] = A2[t];
      B0[t] = B1[t]; B1[t] = B2[t];
    }
  }
#undef LDROW

  // deterministic per-tile pool partials
  sred[tid] = sum0;
  sred[256 + tid] = sum1;
  __syncthreads();
  for (int s = 128; s > 0; s >>= 1) {
    if (tid < s) {
      sred[tid] += sred[tid + s];
      sred[256 + tid] += sred[256 + tid + s];
    }
    __syncthreads();
  }
  if (tid == 0) {
    g_pool_part[(b * HID_ + 2 * c) * 16 + rt] = sred[0];
    g_pool_part[(b * HID_ + 2 * c + 1) * 16 + rt] = sred[256];
  }
}

// ---------------------------------------------------------------------------
// K3: attn matvec + fold into w3: g_wbf[b] = bf16(w3 * attn[b])
// ---------------------------------------------------------------------------
__global__ void k3_attn_fold(const float* __restrict__ w_sca,
                             const float* __restrict__ b_sca,
                             const float* __restrict__ w3) {
  __shared__ float sp[HID_];
  __shared__ float sAttn[HID_];
  int b = blockIdx.x;
  int o = threadIdx.x;  // 128 threads
  float s = 0.f;
  const float* pp = g_pool_part + (b * HID_ + o) * 16;
#pragma unroll
  for (int t = 0; t < 16; t++) s += pp[t];
  sp[o] = s * (1.f / 65536.f);
  __syncthreads();
  float acc = b_sca[o];
  const float* w = w_sca + o * HID_;
#pragma unroll 8
  for (int cc = 0; cc < HID_; cc++) acc += w[cc] * sp[cc];
  sAttn[o] = acc;
  __syncthreads();
  __nv_bfloat16* dst = g_wbf + (size_t)b * 64 * HID_;
  for (int i = o; i < 64 * HID_; i += 128) {
    int k = i & 127;
    dst[i] = __float2bfloat16(w3[i] * sAttn[k]);
  }
}

// ---------------------------------------------------------------------------
// K4: (h2) @ (w3*attn)^T + b3, out = x + beta*h3.
// Split-K: sA holds 64 ch at a time -> 34.8KB smem, launch_bounds(256,5).
// A via ldmatrix.trans, B via ldmatrix (prepped bf16 weights from g_wbf).
// ---------------------------------------------------------------------------
#define K4_OFF_A 0       // h2 bf16 [64 ch][136]    = 17408 B (sO f32[64][132] aliases 0..33792)
#define K4_OFF_W 17408   // wbf bf16 [64 cout][136] = 17408 B
#define K4_SMEM 34816

__global__ void __launch_bounds__(256, 5)
k4_gemm_residual(const float* __restrict__ b3, const float* __restrict__ beta,
                 const float* __restrict__ x, float* __restrict__ out) {
  extern __shared__ char sm4[];
  __nv_bfloat16* sA = (__nv_bfloat16*)(sm4 + K4_OFF_A);   // [64 ch][136]
  __nv_bfloat16* sWB = (__nv_bfloat16*)(sm4 + K4_OFF_W);  // [64 cout][136]
  float* sO = (float*)(sm4);                              // aliases sA+sWB

  const int tid = threadIdx.x;
  const int b = blockIdx.x >> 9;
  const int pix0 = (blockIdx.x & 511) << 7;

  // sWB <- g_wbf[b] (uint4 copy into padded stride)
  {
    const uint4* wsrc = (const uint4*)(g_wbf + (size_t)b * 64 * HID_);
    uint4* sWB4 = (uint4*)sWB;  // stride 17 uint4
    for (int i = tid; i < 1024; i += 256) {
      int o = i >> 4, qq = i & 15;
      sWB4[o * 17 + qq] = wsrc[i];
    }
  }

  const uint4* h2v = (const uint4*)g_h2;
  uint4* sA4 = (uint4*)sA;  // 17 uint4 per row
  size_t base8 = (((size_t)b * HID_) * HW_ + pix0) >> 3;

  const int lane = tid & 31, wid = tid >> 5;
  const int lr = lane >> 2, lc = lane & 3;
  const int MB = (wid & 3) * 32;    // pixel tile (M)
  const int NBc = (wid >> 2) * 32;  // cout tile (N)
  const int lofs = ((lane >> 3) & 1) * 8 + (lane & 7);
  const int lhi = (lane >> 4) * 8;
  const int lkoff = ((lane >> 4) << 3) + (lane & 7);  // trans-ldsm k row
  const int lmoff = ((lane >> 3) & 1) << 3;           // trans-ldsm m half

  float acc[2][4][4];
#pragma unroll
  for (int mt = 0; mt < 2; mt++)
#pragma unroll
    for (int nt = 0; nt < 4; nt++)
#pragma unroll
      for (int r = 0; r < 4; r++) acc[mt][nt][r] = 0.f;

#pragma unroll
  for (int half = 0; half < 2; half++) {
    // sA <- h2 channels [half*64, half*64+64), native [ch][px]
    for (int i = tid; i < 64 * 16; i += 256) {
      int ch = i >> 4, qq = i & 15;
      sA4[ch * 17 + qq] = h2v[base8 + (size_t)(half * 64 + ch) * (HW_ / 8) + qq];
    }
    __syncthreads();
#pragma unroll
    for (int ks = 0; ks < 4; ks++) {
      const int klocal = ks * 16;
      const int kglob = half * 64 + klocal;
      unsigned a[2][4];
      ldsm_trans(a[0], &sA[(klocal + lkoff) * 136 + MB + lmoff]);
      ldsm_trans(a[1], &sA[(klocal + lkoff) * 136 + MB + 16 + lmoff]);
#pragma unroll
      for (int nb = 0; nb < 2; nb++) {
        unsigned bb[4];
        ldsm(bb, &sWB[(NBc + nb * 16 + lofs) * 136 + kglob + lhi]);
        MMA_BF16(acc[0][nb * 2], a[0], bb[0], bb[2]);
        MMA_BF16(acc[1][nb * 2], a[1], bb[0], bb[2]);
        MMA_BF16(acc[0][nb * 2 + 1], a[0], bb[1], bb[3]);
        MMA_BF16(acc[1][nb * 2 + 1], a[1], bb[1], bb[3]);
      }
    }
    __syncthreads();  // before overwriting sA (and before sO epilogue)
  }

  // stage D[px][cout] -> sO[cout][132px]
#pragma unroll
  for (int mt = 0; mt < 2; mt++)
#pragma unroll
    for (int nt = 0; nt < 4; nt++)
#pragma unroll
      for (int r = 0; r < 4; r++) {
        int row = MB + mt * 16 + lr + ((r & 2) ? 8 : 0);  // px
        int col = NBc + nt * 8 + lc * 2 + (r & 1);        // cout
        sO[col * 132 + row] = acc[mt][nt][r];
      }
  __syncthreads();

  // residual + beta, float4 vectorized
  size_t xbase = ((size_t)b * C_) * HW_ + pix0;
  for (int i = tid; i < 64 * 32; i += 256) {
    int o = i >> 5, p4 = (i & 31) * 4;
    float4 hv = *(const float4*)&sO[o * 132 + p4];
    size_t idx = xbase + (size_t)o * HW_ + p4;
    float4 xin = *(const float4*)&x[idx];
    float bbv = b3[o], be = beta[o];
    float4 r;
    r.x = xin.x + (hv.x + bbv) * be;
    r.y = xin.y + (hv.y + bbv) * be;
    r.z = xin.z + (hv.z + bbv) * be;
    r.w = xin.w + (hv.w + bbv) * be;
    *(float4*)&out[idx] = r;
  }
}

// ---------------------------------------------------------------------------
extern "C" void kernel_launch(void* const* d_in, const int* in_sizes, int n_in,
                              void* d_out, int out_size) {
  const float* x = (const float*)d_in[0];
  const float* ln_w = (const float*)d_in[1];
  const float* ln_b = (const float*)d_in[2];
  const float* w1 = (const float*)d_in[3];
  const float* b1 = (const float*)d_in[4];
  const float* w2 = (const float*)d_in[5];
  const float* b2 = (const float*)d_in[6];
  const float* w_sca = (const float*)d_in[7];
  const float* b_sca = (const float*)d_in[8];
  const float* w3 = (const float*)d_in[9];
  const float* b3 = (const float*)d_in[10];
  const float* beta = (const float*)d_in[11];
  float* out = (float*)d_out;

  cudaFuncSetAttribute(k1_ln_gemm_gate,
                       cudaFuncAttributeMaxDynamicSharedMemorySize, K1_SMEM);
  cudaFuncSetAttribute(k4_gemm_residual,
                       cudaFuncAttributeMaxDynamicSharedMemorySize, K4_SMEM);

  k0_prep<<<64, 256>>>(w1);
  k1_ln_gemm_gate<<<4096, 512, K1_SMEM>>>(x, ln_w, ln_b, b1);
  k2_dwconv_gate_pool<<<dim3(16, 64, 8), 256>>>(w2, b2);
  k3_attn_fold<<<8, 128>>>(w_sca, b_sca, w3);
  k4_gemm_residual<<<4096, 256, K4_SMEM>>>(b3, beta, x, out);
}

// round 8
// speedup vs baseline: 1.8842x; 1.0213x over previous
#include <cuda_runtime.h>
#include <cuda_bf16.h>
#include <cstdint>

#define NB_ 8
#define C_ 64
#define HID_ 128
#define HW_ 65536

// Scratch (device globals; no allocation in kernel_launch)
__device__ __nv_bfloat16 g_h1[(size_t)NB_ * HID_ * HW_];
__device__ __nv_bfloat16 g_h2[(size_t)NB_ * HID_ * HW_];
__device__ float g_pool_part[NB_ * HID_ * 16];
__device__ __nv_bfloat16 g_w1bf[256 * 64];          // prepped bf16 w1
__device__ __nv_bfloat16 g_wbf[NB_ * 64 * HID_];    // per-batch bf16 w3*attn

#define MMA_BF16(d, A, b0r, b1r)                                              \
  asm volatile(                                                               \
      "mma.sync.aligned.m16n8k16.row.col.f32.bf16.bf16.f32 "                  \
      "{%0,%1,%2,%3},{%4,%5,%6,%7},{%8,%9},{%0,%1,%2,%3};\n"                  \
      : "+f"((d)[0]), "+f"((d)[1]), "+f"((d)[2]), "+f"((d)[3])                \
      : "r"((A)[0]), "r"((A)[1]), "r"((A)[2]), "r"((A)[3]), "r"(b0r),         \
        "r"(b1r))

__device__ __forceinline__ void ldsm(unsigned (&r)[4], const __nv_bfloat16* p) {
  unsigned addr = (unsigned)__cvta_generic_to_shared(p);
  asm volatile(
      "ldmatrix.sync.aligned.m8n8.x4.shared.b16 {%0,%1,%2,%3}, [%4];"
      : "=r"(r[0]), "=r"(r[1]), "=r"(r[2]), "=r"(r[3])
      : "r"(addr));
}

__device__ __forceinline__ void ldsm_trans(unsigned (&r)[4],
                                           const __nv_bfloat16* p) {
  unsigned addr = (unsigned)__cvta_generic_to_shared(p);
  asm volatile(
      "ldmatrix.sync.aligned.m8n8.x4.trans.shared.b16 {%0,%1,%2,%3}, [%4];"
      : "=r"(r[0]), "=r"(r[1]), "=r"(r[2]), "=r"(r[3])
      : "r"(addr));
}

// ---------------------------------------------------------------------------
// K0: one-time prep: w1 -> bf16
// ---------------------------------------------------------------------------
__global__ void k0_prep(const float* __restrict__ w1) {
  int i = blockIdx.x * 256 + threadIdx.x;  // 64 blocks x 256 = 16384
  g_w1bf[i] = __float2bfloat16(w1[i]);
}

// ---------------------------------------------------------------------------
// K1: LayerNorm + 1x1 conv (64->256, bf16 mma) + SimpleGate -> g_h1 (bf16)
// Block: 64 pixels, 512 threads, 2 blocks/SM (67KB smem, <=64 regs).
// 16 warps = 2 Mtiles(32px) x 8 Npair-tiles(16 pair-cols).
// ---------------------------------------------------------------------------
#define K1_OFF_W 0          // w1 bf16 [256][72]          = 36864 B
#define K1_OFF_A 36864      // xn bf16 [64][72]           =  9216 B
#define K1_OFF_B1 46080     // b1 f32  [256]              =  1024 B
#define K1_OFF_RED 47104    // LN partials f32 [1024]     =  4096 B
#define K1_OFF_H 51200      // h1 stage bf16 [128][68]    = 17408 B
#define K1_SMEM 68608

__global__ void __launch_bounds__(512, 2)
k1_ln_gemm_gate(const float* __restrict__ x, const float* __restrict__ ln_w,
                const float* __restrict__ ln_b, const float* __restrict__ b1) {
  extern __shared__ char sm1[];
  __nv_bfloat16* sW = (__nv_bfloat16*)(sm1 + K1_OFF_W);
  __nv_bfloat16* sA = (__nv_bfloat16*)(sm1 + K1_OFF_A);
  float* sB1 = (float*)(sm1 + K1_OFF_B1);
  float* sRED = (float*)(sm1 + K1_OFF_RED);
  __nv_bfloat16* sH = (__nv_bfloat16*)(sm1 + K1_OFF_H);

  const int tid = threadIdx.x;
  const int b = blockIdx.x >> 10;              // 1024 blocks per image
  const int pix0 = (blockIdx.x & 1023) << 6;   // 64 pixels per block

  // weights -> smem (uint4 copy of prepped bf16)
  {
    const uint4* wsrc = (const uint4*)g_w1bf;  // [256][8 uint4]
    uint4* sW4 = (uint4*)sW;                   // stride 9 uint4 (72 bf16)
    for (int i = tid; i < 2048; i += 512) {
      int rr = i >> 3, q = i & 7;
      sW4[rr * 9 + q] = wsrc[i];
    }
  }
  if (tid < 256) sB1[tid] = b1[tid];

  // load x tile + LayerNorm (8 threads per pixel, 8 channels each)
  const int p = tid & 63, q = tid >> 6;  // q = 0..7
  const float* xb = x + (size_t)b * C_ * HW_ + (size_t)(q * 8) * HW_ + pix0 + p;
  float v[8], s1 = 0.f, s2 = 0.f;
#pragma unroll
  for (int i = 0; i < 8; i++) {
    float t = xb[(size_t)i * HW_];
    v[i] = t;
    s1 += t;
    s2 += t * t;
  }
  sRED[tid] = s1;
  sRED[512 + tid] = s2;
  __syncthreads();
  float t1 = 0.f, t2 = 0.f;
#pragma unroll
  for (int g = 0; g < 8; g++) {
    t1 += sRED[g * 64 + p];
    t2 += sRED[512 + g * 64 + p];
  }
  float mean = t1 * (1.f / 64.f);
  float var = t2 * (1.f / 64.f) - mean * mean;
  float rstd = rsqrtf(var + 1e-6f);
#pragma unroll
  for (int i = 0; i < 8; i++) {
    int c = q * 8 + i;
    float xn = (v[i] - mean) * rstd * ln_w[c] + ln_b[c];
    sA[p * 72 + c] = __float2bfloat16(xn);
  }
  __syncthreads();

  // 16 warps: MB = (wid&1)*32 px, NBc = (wid>>1)*16 pair-cols
  const int lane = tid & 31, wid = tid >> 5;
  const int lr = lane >> 2, lc = lane & 3;
  const int MB = (wid & 1) * 32;
  const int NBc = (wid >> 1) * 16;
  const int lofs = ((lane >> 3) & 1) * 8 + (lane & 7);  // ldsm row-in-tile
  const int lhi = (lane >> 4) * 8;                      // ldsm k-half

  float acc1[2][2][4], acc2[2][2][4];
#pragma unroll
  for (int mt = 0; mt < 2; mt++)
#pragma unroll
    for (int nt = 0; nt < 2; nt++)
#pragma unroll
      for (int r = 0; r < 4; r++) {
        acc1[mt][nt][r] = 0.f;
        acc2[mt][nt][r] = 0.f;
      }

#pragma unroll
  for (int ks = 0; ks < 4; ks++) {
    const int kc = ks * 16;
    unsigned a[2][4];
    ldsm(a[0], &sA[(MB + lofs) * 72 + kc + lhi]);
    ldsm(a[1], &sA[(MB + 16 + lofs) * 72 + kc + lhi]);
    unsigned bb1[4], bb2[4];
    ldsm(bb1, &sW[(NBc + lofs) * 72 + kc + lhi]);
    ldsm(bb2, &sW[(NBc + 128 + lofs) * 72 + kc + lhi]);
#pragma unroll
    for (int mt = 0; mt < 2; mt++) {
      MMA_BF16(acc1[mt][0], a[mt], bb1[0], bb1[2]);
      MMA_BF16(acc1[mt][1], a[mt], bb1[1], bb1[3]);
      MMA_BF16(acc2[mt][0], a[mt], bb2[0], bb2[2]);
      MMA_BF16(acc2[mt][1], a[mt], bb2[1], bb2[3]);
    }
  }

  // gate in-register, stage [ch][pixel] in smem
#pragma unroll
  for (int mt = 0; mt < 2; mt++)
#pragma unroll
    for (int nt = 0; nt < 2; nt++)
#pragma unroll
      for (int r = 0; r < 4; r++) {
        int row = MB + mt * 16 + lr + ((r & 2) ? 8 : 0);  // px 0..63
        int col = NBc + nt * 8 + lc * 2 + (r & 1);        // pair-col 0..127
        float y1 = acc1[mt][nt][r] + sB1[col];
        float y2 = acc2[mt][nt][r] + sB1[col + 128];
        sH[col * 68 + row] = __float2bfloat16(y1 * y2);
      }
  __syncthreads();

  // coalesced write-out (uint2 = 4 pixels): 128 ch x 16 uint2
  const uint2* sH2 = (const uint2*)sH;            // stride 17 uint2/row
  uint2* out2 = (uint2*)g_h1;
  size_t base2 = (((size_t)b * HID_) * HW_ + pix0) >> 2;
  for (int i = tid; i < 128 * 16; i += 512) {
    int ch = i >> 4, j2 = i & 15;
    out2[base2 + (size_t)ch * (HW_ / 4) + j2] = sH2[ch * 17 + j2];
  }
}

// ---------------------------------------------------------------------------
// K2: grouped 3x3 depthwise (2 out per group) + gate + pool partials
// Full-width row tiles: 256 wide x 16 high; halo only in y.
// ---------------------------------------------------------------------------
__global__ void __launch_bounds__(256)
k2_dwconv_gate_pool(const float* __restrict__ w2, const float* __restrict__ b2) {
  __shared__ __nv_bfloat16 sI[2][18 * 272];  // data at cols 8..263
  __shared__ float swb[40];
  __shared__ float sred[512];

  const int rt = blockIdx.x;   // 0..15 row tile
  const int c = blockIdx.y;    // 0..63 channel pair
  const int b = blockIdx.z;    // 0..7
  const int tid = threadIdx.x;

  if (tid < 40) {
    int widx = (tid < 36) ? (tid / 9) : (tid - 36);
    int o = (widx < 2) ? (2 * c + widx) : (128 + 2 * c + widx - 2);
    swb[tid] = (tid < 36) ? w2[o * 9 + tid % 9] : b2[o];
  }

  const int gy0 = rt * 16 - 1;
  const uint4* src0 = (const uint4*)(g_h1 + ((size_t)(b * HID_ + c)) * HW_);
  const uint4* src1 = (const uint4*)(g_h1 + ((size_t)(b * HID_ + 64 + c)) * HW_);
  for (int i = tid; i < 1152; i += 256) {   // 2ch * 18 rows * 32 uint4
    int ch = (i >= 576) ? 1 : 0;
    int j = i - ch * 576;
    int row = j >> 5, k8 = j & 31;
    int gy = gy0 + row;
    uint4 v = make_uint4(0, 0, 0, 0);
    if ((unsigned)gy < 256u) v = (ch ? src1 : src0)[gy * 32 + k8];
    *(uint4*)(&sI[ch][row * 272 + 8 + k8 * 8]) = v;
  }
  if (tid < 72) {  // zero halo cols 7 and 264
    int ch = (tid >= 36) ? 1 : 0;
    int t = tid - ch * 36;
    sI[ch][(t >> 1) * 272 + ((t & 1) ? 264 : 7)] = __float2bfloat16(0.f);
  }
  __syncthreads();

  const int rg = tid >> 6;    // 0..3
  const int cb = tid & 63;    // 0..63
  const int r0 = rg * 4;
  const int sc = 8 + cb * 4;

  float w0[9], w1v[9], w2v[9], w3v[9];
#pragma unroll
  for (int t = 0; t < 9; t++) {
    w0[t] = swb[t];
    w1v[t] = swb[9 + t];
    w2v[t] = swb[18 + t];
    w3v[t] = swb[27 + t];
  }
  const float bs0 = swb[36], bs1 = swb[37], bs2 = swb[38], bs3 = swb[39];

#define LDROW(ch, row, r)                                                     \
  {                                                                           \
    const __nv_bfloat162* p_ =                                                \
        (const __nv_bfloat162*)(&sI[ch][(row)*272 + sc - 2]);                 \
    float2 q0 = __bfloat1622float2(p_[0]);                                    \
    float2 q1 = __bfloat1622float2(p_[1]);                                    \
    float2 q2 = __bfloat1622float2(p_[2]);                                    \
    float2 q3 = __bfloat1622float2(p_[3]);                                    \
    r[0] = q0.y; r[1] = q1.x; r[2] = q1.y;                                    \
    r[3] = q2.x; r[4] = q2.y; r[5] = q3.x;                                    \
  }

  float A0[6], A1[6], A2[6], B0[6], B1[6], B2[6];
  LDROW(0, r0, A0);
  LDROW(0, r0 + 1, A1);
  LDROW(1, r0, B0);
  LDROW(1, r0 + 1, B1);

  float sum0 = 0.f, sum1 = 0.f;
  size_t obase =
      ((size_t)(b * HID_ + 2 * c)) * HW_ + (size_t)(rt * 16 + r0) * 256 + cb * 4;

#pragma unroll
  for (int orow = 0; orow < 4; orow++) {
    LDROW(0, r0 + orow + 2, A2);
    LDROW(1, r0 + orow + 2, B2);
    float a0[4] = {0, 0, 0, 0}, a1[4] = {0, 0, 0, 0};
    float c0[4] = {0, 0, 0, 0}, c1[4] = {0, 0, 0, 0};
#pragma unroll
    for (int k = 0; k < 4; k++) {
#pragma unroll
      for (int dx = 0; dx < 3; dx++) {
        a0[k] += w0[dx] * A0[k + dx] + w0[3 + dx] * A1[k + dx] + w0[6 + dx] * A2[k + dx];
        a1[k] += w1v[dx] * A0[k + dx] + w1v[3 + dx] * A1[k + dx] + w1v[6 + dx] * A2[k + dx];
        c0[k] += w2v[dx] * B0[k + dx] + w2v[3 + dx] * B1[k + dx] + w2v[6 + dx] * B2[k + dx];
        c1[k] += w3v[dx] * B0[k + dx] + w3v[3 + dx] * B1[k + dx] + w3v[6 + dx] * B2[k + dx];
      }
    }
    alignas(8) __nv_bfloat16 o0[4], o1[4];
#pragma unroll
    for (int k = 0; k < 4; k++) {
      float h0 = (a0[k] + bs0) * (c0[k] + bs2);
      float h1 = (a1[k] + bs1) * (c1[k] + bs3);
      sum0 += h0;
      sum1 += h1;
      o0[k] = __float2bfloat16(h0);
      o1[k] = __float2bfloat16(h1);
    }
    *(uint2*)&g_h2[obase + (size_t)orow * 256] = *(const uint2*)o0;
    *(uint2*)&g_h2[obase + HW_ + (size_t)orow * 256] = *(const uint2*)o1;
#pragma unroll
    for (int t = 0; t < 6; t++) {
      A0[t] = A1[t]; A1[t] = A2[t];
      B0[t] = B1[t]; B1[t] = B2[t];
    }
  }
#undef LDROW

  // deterministic per-tile pool partials
  sred[tid] = sum0;
  sred[256 + tid] = sum1;
  __syncthreads();
  for (int s = 128; s > 0; s >>= 1) {
    if (tid < s) {
      sred[tid] += sred[tid + s];
      sred[256 + tid] += sred[256 + tid + s];
    }
    __syncthreads();
  }
  if (tid == 0) {
    g_pool_part[(b * HID_ + 2 * c) * 16 + rt] = sred[0];
    g_pool_part[(b * HID_ + 2 * c + 1) * 16 + rt] = sred[256];
  }
}

// ---------------------------------------------------------------------------
// K3: attn matvec + fold into w3: g_wbf[b] = bf16(w3 * attn[b])
// 1024 threads: pool+matvec on t<128, fold parallel across all threads.
// ---------------------------------------------------------------------------
__global__ void __launch_bounds__(1024)
k3_attn_fold(const float* __restrict__ w_sca, const float* __restrict__ b_sca,
             const float* __restrict__ w3) {
  __shared__ float sp[HID_];
  __shared__ float sAttn[HID_];
  const int b = blockIdx.x;
  const int t = threadIdx.x;
  if (t < HID_) {
    float s = 0.f;
    const float* pp = g_pool_part + (b * HID_ + t) * 16;
#pragma unroll
    for (int k = 0; k < 16; k++) s += pp[k];
    sp[t] = s * (1.f / 65536.f);
  }
  __syncthreads();
  if (t < HID_) {
    float acc = b_sca[t];
    const float* w = w_sca + t * HID_;
#pragma unroll 16
    for (int cc = 0; cc < HID_; cc++) acc += w[cc] * sp[cc];
    sAttn[t] = acc;
  }
  __syncthreads();
  __nv_bfloat16* dst = g_wbf + (size_t)b * 64 * HID_;
#pragma unroll
  for (int j = 0; j < 8; j++) {
    int i = t + j * 1024;
    dst[i] = __float2bfloat16(w3[i] * sAttn[i & 127]);
  }
}

// ---------------------------------------------------------------------------
// K4: (h2) @ (w3*attn)^T + b3, out = x + beta*h3.
// Split-K: sA holds 64 ch at a time -> 34.8KB smem, launch_bounds(256,5).
// A via ldmatrix.trans, B via ldmatrix (prepped bf16 weights from g_wbf).
// ---------------------------------------------------------------------------
#define K4_OFF_A 0       // h2 bf16 [64 ch][136]    = 17408 B (sO f32[64][132] aliases 0..33792)
#define K4_OFF_W 17408   // wbf bf16 [64 cout][136] = 17408 B
#define K4_SMEM 34816

__global__ void __launch_bounds__(256, 5)
k4_gemm_residual(const float* __restrict__ b3, const float* __restrict__ beta,
                 const float* __restrict__ x, float* __restrict__ out) {
  extern __shared__ char sm4[];
  __nv_bfloat16* sA = (__nv_bfloat16*)(sm4 + K4_OFF_A);   // [64 ch][136]
  __nv_bfloat16* sWB = (__nv_bfloat16*)(sm4 + K4_OFF_W);  // [64 cout][136]
  float* sO = (float*)(sm4);                              // aliases sA+sWB

  const int tid = threadIdx.x;
  const int b = blockIdx.x >> 9;
  const int pix0 = (blockIdx.x & 511) << 7;

  // sWB <- g_wbf[b] (uint4 copy into padded stride)
  {
    const uint4* wsrc = (const uint4*)(g_wbf + (size_t)b * 64 * HID_);
    uint4* sWB4 = (uint4*)sWB;  // stride 17 uint4
    for (int i = tid; i < 1024; i += 256) {
      int o = i >> 4, qq = i & 15;
      sWB4[o * 17 + qq] = wsrc[i];
    }
  }

  const uint4* h2v = (const uint4*)g_h2;
  uint4* sA4 = (uint4*)sA;  // 17 uint4 per row
  size_t base8 = (((size_t)b * HID_) * HW_ + pix0) >> 3;

  const int lane = tid & 31, wid = tid >> 5;
  const int lr = lane >> 2, lc = lane & 3;
  const int MB = (wid & 3) * 32;    // pixel tile (M)
  const int NBc = (wid >> 2) * 32;  // cout tile (N)
  const int lofs = ((lane >> 3) & 1) * 8 + (lane & 7);
  const int lhi = (lane >> 4) * 8;
  const int lkoff = ((lane >> 4) << 3) + (lane & 7);  // trans-ldsm k row
  const int lmoff = ((lane >> 3) & 1) << 3;           // trans-ldsm m half

  float acc[2][4][4];
#pragma unroll
  for (int mt = 0; mt < 2; mt++)
#pragma unroll
    for (int nt = 0; nt < 4; nt++)
#pragma unroll
      for (int r = 0; r < 4; r++) acc[mt][nt][r] = 0.f;

#pragma unroll
  for (int half = 0; half < 2; half++) {
    // sA <- h2 channels [half*64, half*64+64), native [ch][px]
    for (int i = tid; i < 64 * 16; i += 256) {
      int ch = i >> 4, qq = i & 15;
      sA4[ch * 17 + qq] = h2v[base8 + (size_t)(half * 64 + ch) * (HW_ / 8) + qq];
    }
    __syncthreads();
#pragma unroll
    for (int ks = 0; ks < 4; ks++) {
      const int klocal = ks * 16;
      const int kglob = half * 64 + klocal;
      unsigned a[2][4];
      ldsm_trans(a[0], &sA[(klocal + lkoff) * 136 + MB + lmoff]);
      ldsm_trans(a[1], &sA[(klocal + lkoff) * 136 + MB + 16 + lmoff]);
#pragma unroll
      for (int nb = 0; nb < 2; nb++) {
        unsigned bb[4];
        ldsm(bb, &sWB[(NBc + nb * 16 + lofs) * 136 + kglob + lhi]);
        MMA_BF16(acc[0][nb * 2], a[0], bb[0], bb[2]);
        MMA_BF16(acc[1][nb * 2], a[1], bb[0], bb[2]);
        MMA_BF16(acc[0][nb * 2 + 1], a[0], bb[1], bb[3]);
        MMA_BF16(acc[1][nb * 2 + 1], a[1], bb[1], bb[3]);
      }
    }
    __syncthreads();  // before overwriting sA (and before sO epilogue)
  }

  // stage D[px][cout] -> sO[cout][132px]
#pragma unroll
  for (int mt = 0; mt < 2; mt++)
#pragma unroll
    for (int nt = 0; nt < 4; nt++)
#pragma unroll
      for (int r = 0; r < 4; r++) {
        int row = MB + mt * 16 + lr + ((r & 2) ? 8 : 0);  // px
        int col = NBc + nt * 8 + lc * 2 + (r & 1);        // cout
        sO[col * 132 + row] = acc[mt][nt][r];
      }
  __syncthreads();

  // residual + beta, float4 vectorized
  size_t xbase = ((size_t)b * C_) * HW_ + pix0;
  for (int i = tid; i < 64 * 32; i += 256) {
    int o = i >> 5, p4 = (i & 31) * 4;
    float4 hv = *(const float4*)&sO[o * 132 + p4];
    size_t idx = xbase + (size_t)o * HW_ + p4;
    float4 xin = *(const float4*)&x[idx];
    float bbv = b3[o], be = beta[o];
    float4 r;
    r.x = xin.x + (hv.x + bbv) * be;
    r.y = xin.y + (hv.y + bbv) * be;
    r.z = xin.z + (hv.z + bbv) * be;
    r.w = xin.w + (hv.w + bbv) * be;
    *(float4*)&out[idx] = r;
  }
}

// ---------------------------------------------------------------------------
extern "C" void kernel_launch(void* const* d_in, const int* in_sizes, int n_in,
                              void* d_out, int out_size) {
  const float* x = (const float*)d_in[0];
  const float* ln_w = (const float*)d_in[1];
  const float* ln_b = (const float*)d_in[2];
  const float* w1 = (const float*)d_in[3];
  const float* b1 = (const float*)d_in[4];
  const float* w2 = (const float*)d_in[5];
  const float* b2 = (const float*)d_in[6];
  const float* w_sca = (const float*)d_in[7];
  const float* b_sca = (const float*)d_in[8];
  const float* w3 = (const float*)d_in[9];
  const float* b3 = (const float*)d_in[10];
  const float* beta = (const float*)d_in[11];
  float* out = (float*)d_out;

  cudaFuncSetAttribute(k1_ln_gemm_gate,
                       cudaFuncAttributeMaxDynamicSharedMemorySize, K1_SMEM);
  cudaFuncSetAttribute(k4_gemm_residual,
                       cudaFuncAttributeMaxDynamicSharedMemorySize, K4_SMEM);

  k0_prep<<<64, 256>>>(w1);
  k1_ln_gemm_gate<<<8192, 512, K1_SMEM>>>(x, ln_w, ln_b, b1);
  k2_dwconv_gate_pool<<<dim3(16, 64, 8), 256>>>(w2, b2);
  k3_attn_fold<<<8, 1024>>>(w_sca, b_sca, w3);
  k4_gemm_residual<<<4096, 256, K4_SMEM>>>(b3, beta, x, out);
}

// round 9
// speedup vs baseline: 1.9970x; 1.0599x over previous
#include <cuda_runtime.h>
#include <cuda_bf16.h>
#include <cstdint>

#define NB_ 8
#define C_ 64
#define HID_ 128
#define HW_ 65536

// Scratch (device globals; no allocation in kernel_launch)
__device__ __nv_bfloat16 g_h1[(size_t)NB_ * HID_ * HW_];
__device__ __nv_bfloat16 g_h2[(size_t)NB_ * HID_ * HW_];
__device__ float g_pool_part[NB_ * HID_ * 16];
__device__ __nv_bfloat16 g_w1bf[256 * 64];          // prepped bf16 w1
__device__ __nv_bfloat16 g_wbf[NB_ * 64 * HID_];    // per-batch bf16 w3*attn

#define MMA_BF16(d, A, b0r, b1r)                                              \
  asm volatile(                                                               \
      "mma.sync.aligned.m16n8k16.row.col.f32.bf16.bf16.f32 "                  \
      "{%0,%1,%2,%3},{%4,%5,%6,%7},{%8,%9},{%0,%1,%2,%3};\n"                  \
      : "+f"((d)[0]), "+f"((d)[1]), "+f"((d)[2]), "+f"((d)[3])                \
      : "r"((A)[0]), "r"((A)[1]), "r"((A)[2]), "r"((A)[3]), "r"(b0r),         \
        "r"(b1r))

__device__ __forceinline__ void ldsm(unsigned (&r)[4], const __nv_bfloat16* p) {
  unsigned addr = (unsigned)__cvta_generic_to_shared(p);
  asm volatile(
      "ldmatrix.sync.aligned.m8n8.x4.shared.b16 {%0,%1,%2,%3}, [%4];"
      : "=r"(r[0]), "=r"(r[1]), "=r"(r[2]), "=r"(r[3])
      : "r"(addr));
}

__device__ __forceinline__ void ldsm_trans(unsigned (&r)[4],
                                           const __nv_bfloat16* p) {
  unsigned addr = (unsigned)__cvta_generic_to_shared(p);
  asm volatile(
      "ldmatrix.sync.aligned.m8n8.x4.trans.shared.b16 {%0,%1,%2,%3}, [%4];"
      : "=r"(r[0]), "=r"(r[1]), "=r"(r[2]), "=r"(r[3])
      : "r"(addr));
}

// ---------------------------------------------------------------------------
// K0: one-time prep: w1 -> bf16
// ---------------------------------------------------------------------------
__global__ void k0_prep(const float* __restrict__ w1) {
  int i = blockIdx.x * 256 + threadIdx.x;  // 64 blocks x 256 = 16384
  g_w1bf[i] = __float2bfloat16(w1[i]);
}

// ---------------------------------------------------------------------------
// K1: LayerNorm + 1x1 conv (64->256, bf16 mma) + SimpleGate -> g_h1 (bf16)
// PERSISTENT: grid=296 (2 blocks/SM), weights loaded ONCE per block,
// each block grid-strides over 8192 tiles of 64 pixels.
// ---------------------------------------------------------------------------
#define K1_OFF_W 0          // w1 bf16 [256][72]          = 36864 B
#define K1_OFF_A 36864      // xn bf16 [64][72]           =  9216 B
#define K1_OFF_B1 46080     // b1 f32  [256]              =  1024 B
#define K1_OFF_RED 47104    // LN partials f32 [1024]     =  4096 B
#define K1_OFF_H 51200      // h1 stage bf16 [128][68]    = 17408 B
#define K1_SMEM 68608
#define K1_GRID 296

__global__ void __launch_bounds__(512, 2)
k1_ln_gemm_gate(const float* __restrict__ x, const float* __restrict__ ln_w,
                const float* __restrict__ ln_b, const float* __restrict__ b1) {
  extern __shared__ char sm1[];
  __nv_bfloat16* sW = (__nv_bfloat16*)(sm1 + K1_OFF_W);
  __nv_bfloat16* sA = (__nv_bfloat16*)(sm1 + K1_OFF_A);
  float* sB1 = (float*)(sm1 + K1_OFF_B1);
  float* sRED = (float*)(sm1 + K1_OFF_RED);
  __nv_bfloat16* sH = (__nv_bfloat16*)(sm1 + K1_OFF_H);

  const int tid = threadIdx.x;

  // weights -> smem ONCE (uint4 copy of prepped bf16)
  {
    const uint4* wsrc = (const uint4*)g_w1bf;  // [256][8 uint4]
    uint4* sW4 = (uint4*)sW;                   // stride 9 uint4 (72 bf16)
    for (int i = tid; i < 2048; i += 512) {
      int rr = i >> 3, q = i & 7;
      sW4[rr * 9 + q] = wsrc[i];
    }
  }
  if (tid < 256) sB1[tid] = b1[tid];

  const int p = tid & 63, q = tid >> 6;  // q = 0..7
  const int lane = tid & 31, wid = tid >> 5;
  const int lr = lane >> 2, lc = lane & 3;
  const int MB = (wid & 1) * 32;
  const int NBc = (wid >> 1) * 16;
  const int lofs = ((lane >> 3) & 1) * 8 + (lane & 7);  // ldsm row-in-tile
  const int lhi = (lane >> 4) * 8;                      // ldsm k-half

  for (int tile = blockIdx.x; tile < 8192; tile += K1_GRID) {
    const int b = tile >> 10;               // 1024 tiles per image
    const int pix0 = (tile & 1023) << 6;    // 64 pixels per tile

    // load x tile + LayerNorm (8 threads per pixel, 8 channels each)
    const float* xb =
        x + (size_t)b * C_ * HW_ + (size_t)(q * 8) * HW_ + pix0 + p;
    float v[8], s1 = 0.f, s2 = 0.f;
#pragma unroll
    for (int i = 0; i < 8; i++) {
      float t = xb[(size_t)i * HW_];
      v[i] = t;
      s1 += t;
      s2 += t * t;
    }
    sRED[tid] = s1;
    sRED[512 + tid] = s2;
    __syncthreads();
    float t1 = 0.f, t2 = 0.f;
#pragma unroll
    for (int g = 0; g < 8; g++) {
      t1 += sRED[g * 64 + p];
      t2 += sRED[512 + g * 64 + p];
    }
    float mean = t1 * (1.f / 64.f);
    float var = t2 * (1.f / 64.f) - mean * mean;
    float rstd = rsqrtf(var + 1e-6f);
#pragma unroll
    for (int i = 0; i < 8; i++) {
      int c = q * 8 + i;
      float xn = (v[i] - mean) * rstd * ln_w[c] + ln_b[c];
      sA[p * 72 + c] = __float2bfloat16(xn);
    }
    __syncthreads();

    float acc1[2][2][4], acc2[2][2][4];
#pragma unroll
    for (int mt = 0; mt < 2; mt++)
#pragma unroll
      for (int nt = 0; nt < 2; nt++)
#pragma unroll
        for (int r = 0; r < 4; r++) {
          acc1[mt][nt][r] = 0.f;
          acc2[mt][nt][r] = 0.f;
        }

#pragma unroll
    for (int ks = 0; ks < 4; ks++) {
      const int kc = ks * 16;
      unsigned a[2][4];
      ldsm(a[0], &sA[(MB + lofs) * 72 + kc + lhi]);
      ldsm(a[1], &sA[(MB + 16 + lofs) * 72 + kc + lhi]);
      unsigned bb1[4], bb2[4];
      ldsm(bb1, &sW[(NBc + lofs) * 72 + kc + lhi]);
      ldsm(bb2, &sW[(NBc + 128 + lofs) * 72 + kc + lhi]);
#pragma unroll
      for (int mt = 0; mt < 2; mt++) {
        MMA_BF16(acc1[mt][0], a[mt], bb1[0], bb1[2]);
        MMA_BF16(acc1[mt][1], a[mt], bb1[1], bb1[3]);
        MMA_BF16(acc2[mt][0], a[mt], bb2[0], bb2[2]);
        MMA_BF16(acc2[mt][1], a[mt], bb2[1], bb2[3]);
      }
    }

    // gate in-register, stage [ch][pixel] in smem
#pragma unroll
    for (int mt = 0; mt < 2; mt++)
#pragma unroll
      for (int nt = 0; nt < 2; nt++)
#pragma unroll
        for (int r = 0; r < 4; r++) {
          int row = MB + mt * 16 + lr + ((r & 2) ? 8 : 0);  // px 0..63
          int col = NBc + nt * 8 + lc * 2 + (r & 1);        // pair-col
          float y1 = acc1[mt][nt][r] + sB1[col];
          float y2 = acc2[mt][nt][r] + sB1[col + 128];
          sH[col * 68 + row] = __float2bfloat16(y1 * y2);
        }
    __syncthreads();

    // coalesced write-out (uint2 = 4 pixels): 128 ch x 16 uint2
    const uint2* sH2 = (const uint2*)sH;  // stride 17 uint2/row
    uint2* out2 = (uint2*)g_h1;
    size_t base2 = (((size_t)b * HID_) * HW_ + pix0) >> 2;
    for (int i = tid; i < 128 * 16; i += 512) {
      int ch = i >> 4, j2 = i & 15;
      out2[base2 + (size_t)ch * (HW_ / 4) + j2] = sH2[ch * 17 + j2];
    }
    // next iteration's sRED write is safe: all sRED reads were before the
    // second barrier above; sA/sH writes are behind their own barriers.
  }
}

// ---------------------------------------------------------------------------
// K2: grouped 3x3 depthwise (2 out per group) + gate + pool partials
// Full-width row tiles: 256 wide x 16 high; halo only in y.
// ---------------------------------------------------------------------------
__global__ void __launch_bounds__(256)
k2_dwconv_gate_pool(const float* __restrict__ w2, const float* __restrict__ b2) {
  __shared__ __nv_bfloat16 sI[2][18 * 272];  // data at cols 8..263
  __shared__ float swb[40];
  __shared__ float sred[512];

  const int rt = blockIdx.x;   // 0..15 row tile
  const int c = blockIdx.y;    // 0..63 channel pair
  const int b = blockIdx.z;    // 0..7
  const int tid = threadIdx.x;

  if (tid < 40) {
    int widx = (tid < 36) ? (tid / 9) : (tid - 36);
    int o = (widx < 2) ? (2 * c + widx) : (128 + 2 * c + widx - 2);
    swb[tid] = (tid < 36) ? w2[o * 9 + tid % 9] : b2[o];
  }

  const int gy0 = rt * 16 - 1;
  const uint4* src0 = (const uint4*)(g_h1 + ((size_t)(b * HID_ + c)) * HW_);
  const uint4* src1 = (const uint4*)(g_h1 + ((size_t)(b * HID_ + 64 + c)) * HW_);
  for (int i = tid; i < 1152; i += 256) {   // 2ch * 18 rows * 32 uint4
    int ch = (i >= 576) ? 1 : 0;
    int j = i - ch * 576;
    int row = j >> 5, k8 = j & 31;
    int gy = gy0 + row;
    uint4 v = make_uint4(0, 0, 0, 0);
    if ((unsigned)gy < 256u) v = (ch ? src1 : src0)[gy * 32 + k8];
    *(uint4*)(&sI[ch][row * 272 + 8 + k8 * 8]) = v;
  }
  if (tid < 72) {  // zero halo cols 7 and 264
    int ch = (tid >= 36) ? 1 : 0;
    int t = tid - ch * 36;
    sI[ch][(t >> 1) * 272 + ((t & 1) ? 264 : 7)] = __float2bfloat16(0.f);
  }
  __syncthreads();

  const int rg = tid >> 6;    // 0..3
  const int cb = tid & 63;    // 0..63
  const int r0 = rg * 4;
  const int sc = 8 + cb * 4;

  float w0[9], w1v[9], w2v[9], w3v[9];
#pragma unroll
  for (int t = 0; t < 9; t++) {
    w0[t] = swb[t];
    w1v[t] = swb[9 + t];
    w2v[t] = swb[18 + t];
    w3v[t] = swb[27 + t];
  }
  const float bs0 = swb[36], bs1 = swb[37], bs2 = swb[38], bs3 = swb[39];

#define LDROW(ch, row, r)                                                     \
  {                                                                           \
    const __nv_bfloat162* p_ =                                                \
        (const __nv_bfloat162*)(&sI[ch][(row)*272 + sc - 2]);                 \
    float2 q0 = __bfloat1622float2(p_[0]);                                    \
    float2 q1 = __bfloat1622float2(p_[1]);                                    \
    float2 q2 = __bfloat1622float2(p_[2]);                                    \
    float2 q3 = __bfloat1622float2(p_[3]);                                    \
    r[0] = q0.y; r[1] = q1.x; r[2] = q1.y;                                    \
    r[3] = q2.x; r[4] = q2.y; r[5] = q3.x;                                    \
  }

  float A0[6], A1[6], A2[6], B0[6], B1[6], B2[6];
  LDROW(0, r0, A0);
  LDROW(0, r0 + 1, A1);
  LDROW(1, r0, B0);
  LDROW(1, r0 + 1, B1);

  float sum0 = 0.f, sum1 = 0.f;
  size_t obase =
      ((size_t)(b * HID_ + 2 * c)) * HW_ + (size_t)(rt * 16 + r0) * 256 + cb * 4;

#pragma unroll
  for (int orow = 0; orow < 4; orow++) {
    LDROW(0, r0 + orow + 2, A2);
    LDROW(1, r0 + orow + 2, B2);
    float a0[4] = {0, 0, 0, 0}, a1[4] = {0, 0, 0, 0};
    float c0[4] = {0, 0, 0, 0}, c1[4] = {0, 0, 0, 0};
#pragma unroll
    for (int k = 0; k < 4; k++) {
#pragma unroll
      for (int dx = 0; dx < 3; dx++) {
        a0[k] += w0[dx] * A0[k + dx] + w0[3 + dx] * A1[k + dx] + w0[6 + dx] * A2[k + dx];
        a1[k] += w1v[dx] * A0[k + dx] + w1v[3 + dx] * A1[k + dx] + w1v[6 + dx] * A2[k + dx];
        c0[k] += w2v[dx] * B0[k + dx] + w2v[3 + dx] * B1[k + dx] + w2v[6 + dx] * B2[k + dx];
        c1[k] += w3v[dx] * B0[k + dx] + w3v[3 + dx] * B1[k + dx] + w3v[6 + dx] * B2[k + dx];
      }
    }
    alignas(8) __nv_bfloat16 o0[4], o1[4];
#pragma unroll
    for (int k = 0; k < 4; k++) {
      float h0 = (a0[k] + bs0) * (c0[k] + bs2);
      float h1 = (a1[k] + bs1) * (c1[k] + bs3);
      sum0 += h0;
      sum1 += h1;
      o0[k] = __float2bfloat16(h0);
      o1[k] = __float2bfloat16(h1);
    }
    *(uint2*)&g_h2[obase + (size_t)orow * 256] = *(const uint2*)o0;
    *(uint2*)&g_h2[obase + HW_ + (size_t)orow * 256] = *(const uint2*)o1;
#pragma unroll
    for (int t = 0; t < 6; t++) {
      A0[t] = A1[t]; A1[t] = A2[t];
      B0[t] = B1[t]; B1[t] = B2[t];
    }
  }
#undef LDROW

  // deterministic per-tile pool partials
  sred[tid] = sum0;
  sred[256 + tid] = sum1;
  __syncthreads();
  for (int s = 128; s > 0; s >>= 1) {
    if (tid < s) {
      sred[tid] += sred[tid + s];
      sred[256 + tid] += sred[256 + tid + s];
    }
    __syncthreads();
  }
  if (tid == 0) {
    g_pool_part[(b * HID_ + 2 * c) * 16 + rt] = sred[0];
    g_pool_part[(b * HID_ + 2 * c + 1) * 16 + rt] = sred[256];
  }
}

// ---------------------------------------------------------------------------
// K3: attn matvec + fold into w3: g_wbf[b] = bf16(w3 * attn[b])
// 1024 threads: matvec parallelized 8 threads/output + shfl reduce.
// ---------------------------------------------------------------------------
__global__ void __launch_bounds__(1024)
k3_attn_fold(const float* __restrict__ w_sca, const float* __restrict__ b_sca,
             const float* __restrict__ w3) {
  __shared__ float sp[HID_];
  __shared__ float sAttn[HID_];
  const int b = blockIdx.x;
  const int t = threadIdx.x;
  if (t < HID_) {
    float s = 0.f;
    const float* pp = g_pool_part + (b * HID_ + t) * 16;
#pragma unroll
    for (int k = 0; k < 16; k++) s += pp[k];
    sp[t] = s * (1.f / 65536.f);
  }
  __syncthreads();
  {
    const int o = t >> 3, j = t & 7;  // 8 threads per output row
    const float* w = w_sca + o * HID_ + j * 16;
    const float* spp = sp + j * 16;
    float acc = 0.f;
#pragma unroll
    for (int k = 0; k < 16; k++) acc += w[k] * spp[k];
    acc += __shfl_down_sync(0xffffffffu, acc, 4, 8);
    acc += __shfl_down_sync(0xffffffffu, acc, 2, 8);
    acc += __shfl_down_sync(0xffffffffu, acc, 1, 8);
    if (j == 0) sAttn[o] = acc + b_sca[o];
  }
  __syncthreads();
  __nv_bfloat16* dst = g_wbf + (size_t)b * 64 * HID_;
  const float av = sAttn[t & 127];
#pragma unroll
  for (int j = 0; j < 8; j++) {
    int i = t + j * 1024;  // (i & 127) == (t & 127)
    dst[i] = __float2bfloat16(w3[i] * av);
  }
}

// ---------------------------------------------------------------------------
// K4: (h2) @ (w3*attn)^T + b3, out = x + beta*h3.
// Split-K: sA holds 64 ch at a time -> 34.8KB smem, launch_bounds(256,5).
// ---------------------------------------------------------------------------
#define K4_OFF_A 0       // h2 bf16 [64 ch][136]    = 17408 B (sO aliases)
#define K4_OFF_W 17408   // wbf bf16 [64 cout][136] = 17408 B
#define K4_SMEM 34816

__global__ void __launch_bounds__(256, 5)
k4_gemm_residual(const float* __restrict__ b3, const float* __restrict__ beta,
                 const float* __restrict__ x, float* __restrict__ out) {
  extern __shared__ char sm4[];
  __nv_bfloat16* sA = (__nv_bfloat16*)(sm4 + K4_OFF_A);   // [64 ch][136]
  __nv_bfloat16* sWB = (__nv_bfloat16*)(sm4 + K4_OFF_W);  // [64 cout][136]
  float* sO = (float*)(sm4);                              // aliases sA+sWB

  const int tid = threadIdx.x;
  const int b = blockIdx.x >> 9;
  const int pix0 = (blockIdx.x & 511) << 7;

  // sWB <- g_wbf[b] (uint4 copy into padded stride)
  {
    const uint4* wsrc = (const uint4*)(g_wbf + (size_t)b * 64 * HID_);
    uint4* sWB4 = (uint4*)sWB;  // stride 17 uint4
    for (int i = tid; i < 1024; i += 256) {
      int o = i >> 4, qq = i & 15;
      sWB4[o * 17 + qq] = wsrc[i];
    }
  }

  const uint4* h2v = (const uint4*)g_h2;
  uint4* sA4 = (uint4*)sA;  // 17 uint4 per row
  size_t base8 = (((size_t)b * HID_) * HW_ + pix0) >> 3;

  const int lane = tid & 31, wid = tid >> 5;
  const int lr = lane >> 2, lc = lane & 3;
  const int MB = (wid & 3) * 32;    // pixel tile (M)
  const int NBc = (wid >> 2) * 32;  // cout tile (N)
  const int lofs = ((lane >> 3) & 1) * 8 + (lane & 7);
  const int lhi = (lane >> 4) * 8;
  const int lkoff = ((lane >> 4) << 3) + (lane & 7);  // trans-ldsm k row
  const int lmoff = ((lane >> 3) & 1) << 3;           // trans-ldsm m half

  float acc[2][4][4];
#pragma unroll
  for (int mt = 0; mt < 2; mt++)
#pragma unroll
    for (int nt = 0; nt < 4; nt++)
#pragma unroll
      for (int r = 0; r < 4; r++) acc[mt][nt][r] = 0.f;

#pragma unroll
  for (int half = 0; half < 2; half++) {
    // sA <- h2 channels [half*64, half*64+64), native [ch][px]
    for (int i = tid; i < 64 * 16; i += 256) {
      int ch = i >> 4, qq = i & 15;
      sA4[ch * 17 + qq] = h2v[base8 + (size_t)(half * 64 + ch) * (HW_ / 8) + qq];
    }
    __syncthreads();
#pragma unroll
    for (int ks = 0; ks < 4; ks++) {
      const int klocal = ks * 16;
      const int kglob = half * 64 + klocal;
      unsigned a[2][4];
      ldsm_trans(a[0], &sA[(klocal + lkoff) * 136 + MB + lmoff]);
      ldsm_trans(a[1], &sA[(klocal + lkoff) * 136 + MB + 16 + lmoff]);
#pragma unroll
      for (int nb = 0; nb < 2; nb++) {
        unsigned bb[4];
        ldsm(bb, &sWB[(NBc + nb * 16 + lofs) * 136 + kglob + lhi]);
        MMA_BF16(acc[0][nb * 2], a[0], bb[0], bb[2]);
        MMA_BF16(acc[1][nb * 2], a[1], bb[0], bb[2]);
        MMA_BF16(acc[0][nb * 2 + 1], a[0], bb[1], bb[3]);
        MMA_BF16(acc[1][nb * 2 + 1], a[1], bb[1], bb[3]);
      }
    }
    __syncthreads();  // before overwriting sA (and before sO epilogue)
  }

  // stage D[px][cout] -> sO[cout][132px]
#pragma unroll
  for (int mt = 0; mt < 2; mt++)
#pragma unroll
    for (int nt = 0; nt < 4; nt++)
#pragma unroll
      for (int r = 0; r < 4; r++) {
        int row = MB + mt * 16 + lr + ((r & 2) ? 8 : 0);  // px
        int col = NBc + nt * 8 + lc * 2 + (r & 1);        // cout
        sO[col * 132 + row] = acc[mt][nt][r];
      }
  __syncthreads();

  // residual + beta, float4 vectorized
  size_t xbase = ((size_t)b * C_) * HW_ + pix0;
  for (int i = tid; i < 64 * 32; i += 256) {
    int o = i >> 5, p4 = (i & 31) * 4;
    float4 hv = *(const float4*)&sO[o * 132 + p4];
    size_t idx = xbase + (size_t)o * HW_ + p4;
    float4 xin = *(const float4*)&x[idx];
    float bbv = b3[o], be = beta[o];
    float4 r;
    r.x = xin.x + (hv.x + bbv) * be;
    r.y = xin.y + (hv.y + bbv) * be;
    r.z = xin.z + (hv.z + bbv) * be;
    r.w = xin.w + (hv.w + bbv) * be;
    *(float4*)&out[idx] = r;
  }
}

// ---------------------------------------------------------------------------
extern "C" void kernel_launch(void* const* d_in, const int* in_sizes, int n_in,
                              void* d_out, int out_size) {
  const float* x = (const float*)d_in[0];
  const float* ln_w = (const float*)d_in[1];
  const float* ln_b = (const float*)d_in[2];
  const float* w1 = (const float*)d_in[3];
  const float* b1 = (const float*)d_in[4];
  const float* w2 = (const float*)d_in[5];
  const float* b2 = (const float*)d_in[6];
  const float* w_sca = (const float*)d_in[7];
  const float* b_sca = (const float*)d_in[8];
  const float* w3 = (const float*)d_in[9];
  const float* b3 = (const float*)d_in[10];
  const float* beta = (const float*)d_in[11];
  float* out = (float*)d_out;

  cudaFuncSetAttribute(k1_ln_gemm_gate,
                       cudaFuncAttributeMaxDynamicSharedMemorySize, K1_SMEM);
  cudaFuncSetAttribute(k4_gemm_residual,
                       cudaFuncAttributeMaxDynamicSharedMemorySize, K4_SMEM);

  k0_prep<<<64, 256>>>(w1);
  k1_ln_gemm_gate<<<K1_GRID, 512, K1_SMEM>>>(x, ln_w, ln_b, b1);
  k2_dwconv_gate_pool<<<dim3(16, 64, 8), 256>>>(w2, b2);
  k3_attn_fold<<<8, 1024>>>(w_sca, b_sca, w3);
  k4_gemm_residual<<<4096, 256, K4_SMEM>>>(b3, beta, x, out);
}

// round 10
// speedup vs baseline: 2.1591x; 1.0812x over previous
#include <cuda_runtime.h>
#include <cuda_bf16.h>
#include <cstdint>

#define NB_ 8
#define C_ 64
#define HID_ 128
#define HW_ 65536

// Scratch (device globals; no allocation in kernel_launch)
__device__ __nv_bfloat16 g_h1[(size_t)NB_ * HID_ * HW_];
__device__ __nv_bfloat16 g_h2[(size_t)NB_ * HID_ * HW_];
__device__ float g_pool_part[NB_ * HID_ * 16];
__device__ __nv_bfloat16 g_w1bf[256 * 64];          // prepped bf16 w1
__device__ __nv_bfloat16 g_wbf[NB_ * 64 * HID_];    // per-batch bf16 w3*attn

#define MMA_BF16(d, A, b0r, b1r)                                              \
  asm volatile(                                                               \
      "mma.sync.aligned.m16n8k16.row.col.f32.bf16.bf16.f32 "                  \
      "{%0,%1,%2,%3},{%4,%5,%6,%7},{%8,%9},{%0,%1,%2,%3};\n"                  \
      : "+f"((d)[0]), "+f"((d)[1]), "+f"((d)[2]), "+f"((d)[3])                \
      : "r"((A)[0]), "r"((A)[1]), "r"((A)[2]), "r"((A)[3]), "r"(b0r),         \
        "r"(b1r))

__device__ __forceinline__ void ldsm(unsigned (&r)[4], const __nv_bfloat16* p) {
  unsigned addr = (unsigned)__cvta_generic_to_shared(p);
  asm volatile(
      "ldmatrix.sync.aligned.m8n8.x4.shared.b16 {%0,%1,%2,%3}, [%4];"
      : "=r"(r[0]), "=r"(r[1]), "=r"(r[2]), "=r"(r[3])
      : "r"(addr));
}

__device__ __forceinline__ void ldsm_trans(unsigned (&r)[4],
                                           const __nv_bfloat16* p) {
  unsigned addr = (unsigned)__cvta_generic_to_shared(p);
  asm volatile(
      "ldmatrix.sync.aligned.m8n8.x4.trans.shared.b16 {%0,%1,%2,%3}, [%4];"
      : "=r"(r[0]), "=r"(r[1]), "=r"(r[2]), "=r"(r[3])
      : "r"(addr));
}

__device__ __forceinline__ __nv_bfloat162 u2b(unsigned u) {
  return *reinterpret_cast<__nv_bfloat162*>(&u);
}
__device__ __forceinline__ unsigned b2u(__nv_bfloat162 v) {
  return *reinterpret_cast<unsigned*>(&v);
}

// ---------------------------------------------------------------------------
// K0: one-time prep: w1 -> bf16
// ---------------------------------------------------------------------------
__global__ void k0_prep(const float* __restrict__ w1) {
  int i = blockIdx.x * 256 + threadIdx.x;  // 64 blocks x 256 = 16384
  g_w1bf[i] = __float2bfloat16(w1[i]);
}

// ---------------------------------------------------------------------------
// K1: LayerNorm + 1x1 conv (64->256, bf16 mma) + SimpleGate -> g_h1 (bf16)
// PERSISTENT: grid=296 (2 blocks/SM), weights loaded ONCE per block.
// ---------------------------------------------------------------------------
#define K1_OFF_W 0          // w1 bf16 [256][72]          = 36864 B
#define K1_OFF_A 36864      // xn bf16 [64][72]           =  9216 B
#define K1_OFF_B1 46080     // b1 f32  [256]              =  1024 B
#define K1_OFF_RED 47104    // LN partials f32 [1024]     =  4096 B
#define K1_OFF_H 51200      // h1 stage bf16 [128][68]    = 17408 B
#define K1_SMEM 68608
#define K1_GRID 296

__global__ void __launch_bounds__(512, 2)
k1_ln_gemm_gate(const float* __restrict__ x, const float* __restrict__ ln_w,
                const float* __restrict__ ln_b, const float* __restrict__ b1) {
  extern __shared__ char sm1[];
  __nv_bfloat16* sW = (__nv_bfloat16*)(sm1 + K1_OFF_W);
  __nv_bfloat16* sA = (__nv_bfloat16*)(sm1 + K1_OFF_A);
  float* sB1 = (float*)(sm1 + K1_OFF_B1);
  float* sRED = (float*)(sm1 + K1_OFF_RED);
  __nv_bfloat16* sH = (__nv_bfloat16*)(sm1 + K1_OFF_H);

  const int tid = threadIdx.x;

  // weights -> smem ONCE (uint4 copy of prepped bf16)
  {
    const uint4* wsrc = (const uint4*)g_w1bf;  // [256][8 uint4]
    uint4* sW4 = (uint4*)sW;                   // stride 9 uint4 (72 bf16)
    for (int i = tid; i < 2048; i += 512) {
      int rr = i >> 3, q = i & 7;
      sW4[rr * 9 + q] = wsrc[i];
    }
  }
  if (tid < 256) sB1[tid] = b1[tid];

  const int p = tid & 63, q = tid >> 6;  // q = 0..7
  const int lane = tid & 31, wid = tid >> 5;
  const int lr = lane >> 2, lc = lane & 3;
  const int MB = (wid & 1) * 32;
  const int NBc = (wid >> 1) * 16;
  const int lofs = ((lane >> 3) & 1) * 8 + (lane & 7);  // ldsm row-in-tile
  const int lhi = (lane >> 4) * 8;                      // ldsm k-half

  for (int tile = blockIdx.x; tile < 8192; tile += K1_GRID) {
    const int b = tile >> 10;               // 1024 tiles per image
    const int pix0 = (tile & 1023) << 6;    // 64 pixels per tile

    // load x tile + LayerNorm (8 threads per pixel, 8 channels each)
    const float* xb =
        x + (size_t)b * C_ * HW_ + (size_t)(q * 8) * HW_ + pix0 + p;
    float v[8], s1 = 0.f, s2 = 0.f;
#pragma unroll
    for (int i = 0; i < 8; i++) {
      float t = xb[(size_t)i * HW_];
      v[i] = t;
      s1 += t;
      s2 += t * t;
    }
    sRED[tid] = s1;
    sRED[512 + tid] = s2;
    __syncthreads();
    float t1 = 0.f, t2 = 0.f;
#pragma unroll
    for (int g = 0; g < 8; g++) {
      t1 += sRED[g * 64 + p];
      t2 += sRED[512 + g * 64 + p];
    }
    float mean = t1 * (1.f / 64.f);
    float var = t2 * (1.f / 64.f) - mean * mean;
    float rstd = rsqrtf(var + 1e-6f);
#pragma unroll
    for (int i = 0; i < 8; i++) {
      int c = q * 8 + i;
      float xn = (v[i] - mean) * rstd * ln_w[c] + ln_b[c];
      sA[p * 72 + c] = __float2bfloat16(xn);
    }
    __syncthreads();

    float acc1[2][2][4], acc2[2][2][4];
#pragma unroll
    for (int mt = 0; mt < 2; mt++)
#pragma unroll
      for (int nt = 0; nt < 2; nt++)
#pragma unroll
        for (int r = 0; r < 4; r++) {
          acc1[mt][nt][r] = 0.f;
          acc2[mt][nt][r] = 0.f;
        }

#pragma unroll
    for (int ks = 0; ks < 4; ks++) {
      const int kc = ks * 16;
      unsigned a[2][4];
      ldsm(a[0], &sA[(MB + lofs) * 72 + kc + lhi]);
      ldsm(a[1], &sA[(MB + 16 + lofs) * 72 + kc + lhi]);
      unsigned bb1[4], bb2[4];
      ldsm(bb1, &sW[(NBc + lofs) * 72 + kc + lhi]);
      ldsm(bb2, &sW[(NBc + 128 + lofs) * 72 + kc + lhi]);
#pragma unroll
      for (int mt = 0; mt < 2; mt++) {
        MMA_BF16(acc1[mt][0], a[mt], bb1[0], bb1[2]);
        MMA_BF16(acc1[mt][1], a[mt], bb1[1], bb1[3]);
        MMA_BF16(acc2[mt][0], a[mt], bb2[0], bb2[2]);
        MMA_BF16(acc2[mt][1], a[mt], bb2[1], bb2[3]);
      }
    }

    // gate in-register, stage [ch][pixel] in smem
#pragma unroll
    for (int mt = 0; mt < 2; mt++)
#pragma unroll
      for (int nt = 0; nt < 2; nt++)
#pragma unroll
        for (int r = 0; r < 4; r++) {
          int row = MB + mt * 16 + lr + ((r & 2) ? 8 : 0);  // px 0..63
          int col = NBc + nt * 8 + lc * 2 + (r & 1);        // pair-col
          float y1 = acc1[mt][nt][r] + sB1[col];
          float y2 = acc2[mt][nt][r] + sB1[col + 128];
          sH[col * 68 + row] = __float2bfloat16(y1 * y2);
        }
    __syncthreads();

    // coalesced write-out (uint2 = 4 pixels): 128 ch x 16 uint2
    const uint2* sH2 = (const uint2*)sH;  // stride 17 uint2/row
    uint2* out2 = (uint2*)g_h1;
    size_t base2 = (((size_t)b * HID_) * HW_ + pix0) >> 2;
    for (int i = tid; i < 128 * 16; i += 512) {
      int ch = i >> 4, j2 = i & 15;
      out2[base2 + (size_t)ch * (HW_ / 4) + j2] = sH2[ch * 17 + j2];
    }
  }
}

// ---------------------------------------------------------------------------
// K2: grouped 3x3 depthwise + gate + pool partials, bf16x2 SIMD arithmetic.
// Full-width row tiles 256x16; per-thread 4x4 outputs as 2-px pairs.
// ---------------------------------------------------------------------------
__global__ void __launch_bounds__(256)
k2_dwconv_gate_pool(const float* __restrict__ w2, const float* __restrict__ b2) {
  __shared__ __nv_bfloat16 sI[2][18 * 272];  // data at cols 8..263
  __shared__ float swb[40];
  __shared__ float sred[512];

  const int rt = blockIdx.x;   // 0..15 row tile
  const int c = blockIdx.y;    // 0..63 channel pair
  const int b = blockIdx.z;    // 0..7
  const int tid = threadIdx.x;

  if (tid < 40) {
    int widx = (tid < 36) ? (tid / 9) : (tid - 36);
    int o = (widx < 2) ? (2 * c + widx) : (128 + 2 * c + widx - 2);
    swb[tid] = (tid < 36) ? w2[o * 9 + tid % 9] : b2[o];
  }

  const int gy0 = rt * 16 - 1;
  const uint4* src0 = (const uint4*)(g_h1 + ((size_t)(b * HID_ + c)) * HW_);
  const uint4* src1 = (const uint4*)(g_h1 + ((size_t)(b * HID_ + 64 + c)) * HW_);
  for (int i = tid; i < 1152; i += 256) {   // 2ch * 18 rows * 32 uint4
    int ch = (i >= 576) ? 1 : 0;
    int j = i - ch * 576;
    int row = j >> 5, k8 = j & 31;
    int gy = gy0 + row;
    uint4 v = make_uint4(0, 0, 0, 0);
    if ((unsigned)gy < 256u) v = (ch ? src1 : src0)[gy * 32 + k8];
    *(uint4*)(&sI[ch][row * 272 + 8 + k8 * 8]) = v;
  }
  if (tid < 72) {  // zero halo cols 7 and 264
    int ch = (tid >= 36) ? 1 : 0;
    int t = tid - ch * 36;
    sI[ch][(t >> 1) * 272 + ((t & 1) ? 264 : 7)] = __float2bfloat16(0.f);
  }
  __syncthreads();

  const int rg = tid >> 6;    // 0..3
  const int cb = tid & 63;    // 0..63
  const int r0 = rg * 4;
  const int sc = 8 + cb * 4;

  // packed weights (both halves identical) + bias packs
  __nv_bfloat162 wp[36];
#pragma unroll
  for (int t = 0; t < 36; t++)
    wp[t] = __bfloat162bfloat162(__float2bfloat16(swb[t]));
  const __nv_bfloat162 bp0 = __bfloat162bfloat162(__float2bfloat16(swb[36]));
  const __nv_bfloat162 bp1 = __bfloat162bfloat162(__float2bfloat16(swb[37]));
  const __nv_bfloat162 bp2 = __bfloat162bfloat162(__float2bfloat16(swb[38]));
  const __nv_bfloat162 bp3 = __bfloat162bfloat162(__float2bfloat16(swb[39]));

  // 5 operand pair-regs per row per channel:
  // R[0]=(px-1,px0) R[1]=(px0,px1)... covering dx=-1/0/+1 for pairs (0,1),(2,3)
#define LDROW2(ch, row, R)                                                    \
  {                                                                           \
    const unsigned* pp_ = (const unsigned*)&sI[ch][(row)*272 + sc - 2];       \
    unsigned r0_ = pp_[0], r1_ = pp_[1], r2_ = pp_[2], r3_ = pp_[3];          \
    R[0] = __byte_perm(r0_, r1_, 0x5432);                                     \
    R[1] = r1_;                                                               \
    R[2] = __byte_perm(r1_, r2_, 0x5432);                                     \
    R[3] = r2_;                                                               \
    R[4] = __byte_perm(r2_, r3_, 0x5432);                                     \
  }

  unsigned RA0[5], RA1[5], RA2[5], RB0[5], RB1[5], RB2[5];
  LDROW2(0, r0, RA0);
  LDROW2(0, r0 + 1, RA1);
  LDROW2(1, r0, RB0);
  LDROW2(1, r0 + 1, RB1);

  __nv_bfloat162 sum0p = __bfloat162bfloat162(__float2bfloat16(0.f));
  __nv_bfloat162 sum1p = sum0p;
  size_t obase =
      ((size_t)(b * HID_ + 2 * c)) * HW_ + (size_t)(rt * 16 + r0) * 256 + cb * 4;

#pragma unroll
  for (int orow = 0; orow < 4; orow++) {
    LDROW2(0, r0 + orow + 2, RA2);
    LDROW2(1, r0 + orow + 2, RB2);
    __nv_bfloat162 a0p0 = bp0, a0p1 = bp0, a1p0 = bp1, a1p1 = bp1;
    __nv_bfloat162 c0p0 = bp2, c0p1 = bp2, c1p0 = bp3, c1p1 = bp3;
#pragma unroll
    for (int j = 0; j < 3; j++) {
      const unsigned* A = (j == 0) ? RA0 : (j == 1) ? RA1 : RA2;
      const unsigned* B = (j == 0) ? RB0 : (j == 1) ? RB1 : RB2;
      a0p0 = __hfma2(u2b(A[0]), wp[j * 3 + 0], a0p0);
      a0p0 = __hfma2(u2b(A[1]), wp[j * 3 + 1], a0p0);
      a0p0 = __hfma2(u2b(A[2]), wp[j * 3 + 2], a0p0);
      a0p1 = __hfma2(u2b(A[2]), wp[j * 3 + 0], a0p1);
      a0p1 = __hfma2(u2b(A[3]), wp[j * 3 + 1], a0p1);
      a0p1 = __hfma2(u2b(A[4]), wp[j * 3 + 2], a0p1);
      a1p0 = __hfma2(u2b(A[0]), wp[9 + j * 3 + 0], a1p0);
      a1p0 = __hfma2(u2b(A[1]), wp[9 + j * 3 + 1], a1p0);
      a1p0 = __hfma2(u2b(A[2]), wp[9 + j * 3 + 2], a1p0);
      a1p1 = __hfma2(u2b(A[2]), wp[9 + j * 3 + 0], a1p1);
      a1p1 = __hfma2(u2b(A[3]), wp[9 + j * 3 + 1], a1p1);
      a1p1 = __hfma2(u2b(A[4]), wp[9 + j * 3 + 2], a1p1);
      c0p0 = __hfma2(u2b(B[0]), wp[18 + j * 3 + 0], c0p0);
      c0p0 = __hfma2(u2b(B[1]), wp[18 + j * 3 + 1], c0p0);
      c0p0 = __hfma2(u2b(B[2]), wp[18 + j * 3 + 2], c0p0);
      c0p1 = __hfma2(u2b(B[2]), wp[18 + j * 3 + 0], c0p1);
      c0p1 = __hfma2(u2b(B[3]), wp[18 + j * 3 + 1], c0p1);
      c0p1 = __hfma2(u2b(B[4]), wp[18 + j * 3 + 2], c0p1);
      c1p0 = __hfma2(u2b(B[0]), wp[27 + j * 3 + 0], c1p0);
      c1p0 = __hfma2(u2b(B[1]), wp[27 + j * 3 + 1], c1p0);
      c1p0 = __hfma2(u2b(B[2]), wp[27 + j * 3 + 2], c1p0);
      c1p1 = __hfma2(u2b(B[2]), wp[27 + j * 3 + 0], c1p1);
      c1p1 = __hfma2(u2b(B[3]), wp[27 + j * 3 + 1], c1p1);
      c1p1 = __hfma2(u2b(B[4]), wp[27 + j * 3 + 2], c1p1);
    }
    __nv_bfloat162 h0p0 = __hmul2(a0p0, c0p0), h0p1 = __hmul2(a0p1, c0p1);
    __nv_bfloat162 h1p0 = __hmul2(a1p0, c1p0), h1p1 = __hmul2(a1p1, c1p1);
    uint2 st0, st1;
    st0.x = b2u(h0p0); st0.y = b2u(h0p1);
    st1.x = b2u(h1p0); st1.y = b2u(h1p1);
    *(uint2*)&g_h2[obase + (size_t)orow * 256] = st0;
    *(uint2*)&g_h2[obase + HW_ + (size_t)orow * 256] = st1;
    sum0p = __hadd2(sum0p, __hadd2(h0p0, h0p1));
    sum1p = __hadd2(sum1p, __hadd2(h1p0, h1p1));
#pragma unroll
    for (int t = 0; t < 5; t++) {
      RA0[t] = RA1[t]; RA1[t] = RA2[t];
      RB0[t] = RB1[t]; RB1[t] = RB2[t];
    }
  }
#undef LDROW2

  float sum0 = __bfloat162float(__low2bfloat16(sum0p)) +
               __bfloat162float(__high2bfloat16(sum0p));
  float sum1 = __bfloat162float(__low2bfloat16(sum1p)) +
               __bfloat162float(__high2bfloat16(sum1p));

  // deterministic per-tile pool partials
  sred[tid] = sum0;
  sred[256 + tid] = sum1;
  __syncthreads();
  for (int s = 128; s > 0; s >>= 1) {
    if (tid < s) {
      sred[tid] += sred[tid + s];
      sred[256 + tid] += sred[256 + tid + s];
    }
    __syncthreads();
  }
  if (tid == 0) {
    g_pool_part[(b * HID_ + 2 * c) * 16 + rt] = sred[0];
    g_pool_part[(b * HID_ + 2 * c + 1) * 16 + rt] = sred[256];
  }
}

// ---------------------------------------------------------------------------
// K3: attn matvec + fold into w3: g_wbf[b] = bf16(w3 * attn[b])
// grid (8 batches x 8 fold-splits), 256 threads. matvec redundant per block.
// ---------------------------------------------------------------------------
__global__ void __launch_bounds__(256)
k3_attn_fold(const float* __restrict__ w_sca, const float* __restrict__ b_sca,
             const float* __restrict__ w3) {
  __shared__ float sp[HID_];
  __shared__ float sAttn[HID_];
  const int b = blockIdx.x;
  const int t = threadIdx.x;
  if (t < HID_) {
    float s = 0.f;
    const float* pp = g_pool_part + (b * HID_ + t) * 16;
#pragma unroll
    for (int k = 0; k < 16; k++) s += pp[k];
    sp[t] = s * (1.f / 65536.f);
  }
  __syncthreads();
  {
    const int o = t >> 1, j = t & 1;  // 2 threads per output row
    const float* w = w_sca + o * HID_ + j * 64;
    const float* spp = sp + j * 64;
    float acc = 0.f;
#pragma unroll 16
    for (int k = 0; k < 64; k++) acc += w[k] * spp[k];
    acc += __shfl_down_sync(0xffffffffu, acc, 1, 2);
    if (j == 0) sAttn[o] = acc + b_sca[o];
  }
  __syncthreads();
  __nv_bfloat16* dst = g_wbf + (size_t)b * 64 * HID_;
  const int base = blockIdx.y * 1024;
#pragma unroll
  for (int jj = 0; jj < 4; jj++) {
    int i = base + t + jj * 256;
    dst[i] = __float2bfloat16(w3[i] * sAttn[i & 127]);
  }
}

// ---------------------------------------------------------------------------
// K4: (h2) @ (w3*attn)^T + b3, out = x + beta*h3.
// Split-K: sA holds 64 ch at a time -> 34.8KB smem, launch_bounds(256,5).
// ---------------------------------------------------------------------------
#define K4_OFF_A 0       // h2 bf16 [64 ch][136]    = 17408 B (sO aliases)
#define K4_OFF_W 17408   // wbf bf16 [64 cout][136] = 17408 B
#define K4_SMEM 34816

__global__ void __launch_bounds__(256, 5)
k4_gemm_residual(const float* __restrict__ b3, const float* __restrict__ beta,
                 const float* __restrict__ x, float* __restrict__ out) {
  extern __shared__ char sm4[];
  __nv_bfloat16* sA = (__nv_bfloat16*)(sm4 + K4_OFF_A);   // [64 ch][136]
  __nv_bfloat16* sWB = (__nv_bfloat16*)(sm4 + K4_OFF_W);  // [64 cout][136]
  float* sO = (float*)(sm4);                              // aliases sA+sWB

  const int tid = threadIdx.x;
  const int b = blockIdx.x >> 9;
  const int pix0 = (blockIdx.x & 511) << 7;

  // sWB <- g_wbf[b] (uint4 copy into padded stride)
  {
    const uint4* wsrc = (const uint4*)(g_wbf + (size_t)b * 64 * HID_);
    uint4* sWB4 = (uint4*)sWB;  // stride 17 uint4
    for (int i = tid; i < 1024; i += 256) {
      int o = i >> 4, qq = i & 15;
      sWB4[o * 17 + qq] = wsrc[i];
    }
  }

  const uint4* h2v = (const uint4*)g_h2;
  uint4* sA4 = (uint4*)sA;  // 17 uint4 per row
  size_t base8 = (((size_t)b * HID_) * HW_ + pix0) >> 3;

  const int lane = tid & 31, wid = tid >> 5;
  const int lr = lane >> 2, lc = lane & 3;
  const int MB = (wid & 3) * 32;    // pixel tile (M)
  const int NBc = (wid >> 2) * 32;  // cout tile (N)
  const int lofs = ((lane >> 3) & 1) * 8 + (lane & 7);
  const int lhi = (lane >> 4) * 8;
  const int lkoff = ((lane >> 4) << 3) + (lane & 7);  // trans-ldsm k row
  const int lmoff = ((lane >> 3) & 1) << 3;           // trans-ldsm m half

  float acc[2][4][4];
#pragma unroll
  for (int mt = 0; mt < 2; mt++)
#pragma unroll
    for (int nt = 0; nt < 4; nt++)
#pragma unroll
      for (int r = 0; r < 4; r++) acc[mt][nt][r] = 0.f;

#pragma unroll
  for (int half = 0; half < 2; half++) {
    // sA <- h2 channels [half*64, half*64+64), native [ch][px]
    for (int i = tid; i < 64 * 16; i += 256) {
      int ch = i >> 4, qq = i & 15;
      sA4[ch * 17 + qq] = h2v[base8 + (size_t)(half * 64 + ch) * (HW_ / 8) + qq];
    }
    __syncthreads();
#pragma unroll
    for (int ks = 0; ks < 4; ks++) {
      const int klocal = ks * 16;
      const int kglob = half * 64 + klocal;
      unsigned a[2][4];
      ldsm_trans(a[0], &sA[(klocal + lkoff) * 136 + MB + lmoff]);
      ldsm_trans(a[1], &sA[(klocal + lkoff) * 136 + MB + 16 + lmoff]);
#pragma unroll
      for (int nb = 0; nb < 2; nb++) {
        unsigned bb[4];
        ldsm(bb, &sWB[(NBc + nb * 16 + lofs) * 136 + kglob + lhi]);
        MMA_BF16(acc[0][nb * 2], a[0], bb[0], bb[2]);
        MMA_BF16(acc[1][nb * 2], a[1], bb[0], bb[2]);
        MMA_BF16(acc[0][nb * 2 + 1], a[0], bb[1], bb[3]);
        MMA_BF16(acc[1][nb * 2 + 1], a[1], bb[1], bb[3]);
      }
    }
    __syncthreads();  // before overwriting sA (and before sO epilogue)
  }

  // stage D[px][cout] -> sO[cout][132px]
#pragma unroll
  for (int mt = 0; mt < 2; mt++)
#pragma unroll
    for (int nt = 0; nt < 4; nt++)
#pragma unroll
      for (int r = 0; r < 4; r++) {
        int row = MB + mt * 16 + lr + ((r & 2) ? 8 : 0);  // px
        int col = NBc + nt * 8 + lc * 2 + (r & 1);        // cout
        sO[col * 132 + row] = acc[mt][nt][r];
      }
  __syncthreads();

  // residual + beta, float4 vectorized
  size_t xbase = ((size_t)b * C_) * HW_ + pix0;
  for (int i = tid; i < 64 * 32; i += 256) {
    int o = i >> 5, p4 = (i & 31) * 4;
    float4 hv = *(const float4*)&sO[o * 132 + p4];
    size_t idx = xbase + (size_t)o * HW_ + p4;
    float4 xin = *(const float4*)&x[idx];
    float bbv = b3[o], be = beta[o];
    float4 r;
    r.x = xin.x + (hv.x + bbv) * be;
    r.y = xin.y + (hv.y + bbv) * be;
    r.z = xin.z + (hv.z + bbv) * be;
    r.w = xin.w + (hv.w + bbv) * be;
    *(float4*)&out[idx] = r;
  }
}

// ---------------------------------------------------------------------------
extern "C" void kernel_launch(void* const* d_in, const int* in_sizes, int n_in,
                              void* d_out, int out_size) {
  const float* x = (const float*)d_in[0];
  const float* ln_w = (const float*)d_in[1];
  const float* ln_b = (const float*)d_in[2];
  const float* w1 = (const float*)d_in[3];
  const float* b1 = (const float*)d_in[4];
  const float* w2 = (const float*)d_in[5];
  const float* b2 = (const float*)d_in[6];
  const float* w_sca = (const float*)d_in[7];
  const float* b_sca = (const float*)d_in[8];
  const float* w3 = (const float*)d_in[9];
  const float* b3 = (const float*)d_in[10];
  const float* beta = (const float*)d_in[11];
  float* out = (float*)d_out;

  cudaFuncSetAttribute(k1_ln_gemm_gate,
                       cudaFuncAttributeMaxDynamicSharedMemorySize, K1_SMEM);
  cudaFuncSetAttribute(k4_gemm_residual,
                       cudaFuncAttributeMaxDynamicSharedMemorySize, K4_SMEM);

  k0_prep<<<64, 256>>>(w1);
  k1_ln_gemm_gate<<<K1_GRID, 512, K1_SMEM>>>(x, ln_w, ln_b, b1);
  k2_dwconv_gate_pool<<<dim3(16, 64, 8), 256>>>(w2, b2);
  k3_attn_fold<<<dim3(8, 8), 256>>>(w_sca, b_sca, w3);
  k4_gemm_residual<<<4096, 256, K4_SMEM>>>(b3, beta, x, out);
}